// round 1
// baseline (speedup 1.0000x reference)
#include <cuda_runtime.h>
#include <math.h>

// Problem constants
#define CD   384          // hidden C
#define TWIN 256          // tokens per window (4*8*8)
#define NWIN 256          // number of windows (4*8*8)
#define NTOK 65536        // NWIN * TWIN
#define NHEADS 6
#define DHEAD 64
#define MLPD 1536
#define DHW 65536         // 16*64*64
#define HW 4096           // 64*64

// -------- scratch (device globals; allocation-free contract) --------
__device__ float g_xw [NTOK * CD];   // gathered windows (residual 1)
__device__ float g_h  [NTOK * CD];   // LN1 output
__device__ float g_q  [NTOK * CD];
__device__ float g_k  [NTOK * CD];
__device__ float g_v  [NTOK * CD];
__device__ float g_att[NTOK * CD];   // attention output
__device__ float g_xw2[NTOK * CD];   // after O-proj residual (residual 2)
__device__ float g_h2 [NTOK * CD];   // LN2 output
__device__ float g_hid[(size_t)NTOK * MLPD];  // MLP hidden
__device__ float g_y  [NTOK * CD];   // final window-space output

// ---------------- gather (shift + window partition) + LN1 ----------------
__global__ void gather_ln1_kernel(const float* __restrict__ x,
                                  const float* __restrict__ gamma,
                                  const float* __restrict__ beta) {
    int n = blockIdx.x;          // token id 0..65535
    int c = threadIdx.x;         // 0..383
    int p = n >> 8, t = n & 255;
    int bd = p >> 6, bh = (p >> 3) & 7, bw = p & 7;
    int td = t >> 6, th = (t >> 3) & 7, tw = t & 7;
    int od = (bd * 4 + td + 2) & 15;   // +SHIFT mod D
    int oh = (bh * 8 + th + 4) & 63;
    int ow = (bw * 8 + tw + 4) & 63;
    int sp = od * HW + oh * 64 + ow;

    float val = x[c * DHW + sp];

    __shared__ float red[12];
    __shared__ float mu_s, rs_s;

    // mean
    float s = val;
    #pragma unroll
    for (int o = 16; o; o >>= 1) s += __shfl_down_sync(0xffffffffu, s, o);
    if ((threadIdx.x & 31) == 0) red[threadIdx.x >> 5] = s;
    __syncthreads();
    if (threadIdx.x < 32) {
        float tsum = (threadIdx.x < 12) ? red[threadIdx.x] : 0.f;
        #pragma unroll
        for (int o = 8; o; o >>= 1) tsum += __shfl_down_sync(0xffffffffu, tsum, o);
        if (threadIdx.x == 0) mu_s = tsum * (1.f / 384.f);
    }
    __syncthreads();
    float mu = mu_s;
    float d = val - mu;

    // variance
    float s2 = d * d;
    #pragma unroll
    for (int o = 16; o; o >>= 1) s2 += __shfl_down_sync(0xffffffffu, s2, o);
    if ((threadIdx.x & 31) == 0) red[threadIdx.x >> 5] = s2;
    __syncthreads();
    if (threadIdx.x < 32) {
        float tsum = (threadIdx.x < 12) ? red[threadIdx.x] : 0.f;
        #pragma unroll
        for (int o = 8; o; o >>= 1) tsum += __shfl_down_sync(0xffffffffu, tsum, o);
        if (threadIdx.x == 0) rs_s = rsqrtf(tsum * (1.f / 384.f) + 1e-5f);
    }
    __syncthreads();

    g_xw[n * CD + c] = val;
    g_h [n * CD + c] = d * rs_s * gamma[c] + beta[c];
}

// ---------------- LN2 (coalesced input) ----------------
__global__ void ln2_kernel(const float* __restrict__ gamma,
                           const float* __restrict__ beta) {
    int n = blockIdx.x;
    int c = threadIdx.x;
    float val = g_xw2[n * CD + c];

    __shared__ float red[12];
    __shared__ float mu_s, rs_s;

    float s = val;
    #pragma unroll
    for (int o = 16; o; o >>= 1) s += __shfl_down_sync(0xffffffffu, s, o);
    if ((threadIdx.x & 31) == 0) red[threadIdx.x >> 5] = s;
    __syncthreads();
    if (threadIdx.x < 32) {
        float tsum = (threadIdx.x < 12) ? red[threadIdx.x] : 0.f;
        #pragma unroll
        for (int o = 8; o; o >>= 1) tsum += __shfl_down_sync(0xffffffffu, tsum, o);
        if (threadIdx.x == 0) mu_s = tsum * (1.f / 384.f);
    }
    __syncthreads();
    float mu = mu_s;
    float d = val - mu;

    float s2 = d * d;
    #pragma unroll
    for (int o = 16; o; o >>= 1) s2 += __shfl_down_sync(0xffffffffu, s2, o);
    if ((threadIdx.x & 31) == 0) red[threadIdx.x >> 5] = s2;
    __syncthreads();
    if (threadIdx.x < 32) {
        float tsum = (threadIdx.x < 12) ? red[threadIdx.x] : 0.f;
        #pragma unroll
        for (int o = 8; o; o >>= 1) tsum += __shfl_down_sync(0xffffffffu, tsum, o);
        if (threadIdx.x == 0) rs_s = rsqrtf(tsum * (1.f / 384.f) + 1e-5f);
    }
    __syncthreads();

    g_h2[n * CD + c] = d * rs_s * gamma[c] + beta[c];
}

// ---------------- SGEMM: C[N,M] = A[N,K] @ B[K,M] + bias (+res / gelu) ----------------
// 128x128x8 tile, 256 threads, 8x8 microtile (4+4 split rows/cols).
// MODE 0: +bias    MODE 1: +bias+res    MODE 2: gelu(+bias)
template<int MODE>
__global__ void __launch_bounds__(256)
gemm_kernel(const float* __restrict__ A, const float* __restrict__ B,
            const float* __restrict__ bias, const float* __restrict__ res,
            float* __restrict__ Cout, int K, int M) {
    __shared__ float As[8][128];
    __shared__ float Bs[8][128];

    int tid = threadIdx.x;
    int brow = blockIdx.x * 128;  // token dim
    int bcol = blockIdx.y * 128;  // output-feature dim
    int tx = tid & 15, ty = tid >> 4;

    int a_r = tid >> 1, a_c = (tid & 1) * 4;
    int b_r = tid >> 5, b_c = (tid & 31) * 4;

    const float* Aptr = A + (size_t)(brow + a_r) * K + a_c;
    const float* Bptr = B + (size_t)b_r * M + bcol + b_c;

    float acc[8][8];
    #pragma unroll
    for (int i = 0; i < 8; i++)
        #pragma unroll
        for (int j = 0; j < 8; j++) acc[i][j] = 0.f;

    for (int k0 = 0; k0 < K; k0 += 8) {
        float4 av = *(const float4*)(Aptr + k0);
        float4 bv = *(const float4*)(Bptr + (size_t)k0 * M);
        As[a_c + 0][a_r] = av.x;
        As[a_c + 1][a_r] = av.y;
        As[a_c + 2][a_r] = av.z;
        As[a_c + 3][a_r] = av.w;
        *(float4*)&Bs[b_r][b_c] = bv;
        __syncthreads();

        #pragma unroll
        for (int kk = 0; kk < 8; kk++) {
            float4 a0 = *(const float4*)&As[kk][ty * 4];
            float4 a1 = *(const float4*)&As[kk][64 + ty * 4];
            float4 b0 = *(const float4*)&Bs[kk][tx * 4];
            float4 b1 = *(const float4*)&Bs[kk][64 + tx * 4];
            float ra[8] = {a0.x, a0.y, a0.z, a0.w, a1.x, a1.y, a1.z, a1.w};
            float rb[8] = {b0.x, b0.y, b0.z, b0.w, b1.x, b1.y, b1.z, b1.w};
            #pragma unroll
            for (int i = 0; i < 8; i++)
                #pragma unroll
                for (int j = 0; j < 8; j++)
                    acc[i][j] += ra[i] * rb[j];
        }
        __syncthreads();
    }

    // epilogue
    #pragma unroll
    for (int i = 0; i < 8; i++) {
        int row = brow + ((i < 4) ? (ty * 4 + i) : (64 + ty * 4 + i - 4));
        #pragma unroll
        for (int jh = 0; jh < 2; jh++) {
            int col0 = bcol + (jh ? (64 + tx * 4) : (tx * 4));
            float4 v;
            float* vp = &v.x;
            #pragma unroll
            for (int j = 0; j < 4; j++) {
                float val = acc[i][jh * 4 + j] + bias[col0 + j];
                if (MODE == 1) val += res[(size_t)row * M + col0 + j];
                if (MODE == 2) val = 0.5f * val * (1.0f + erff(val * 0.7071067811865476f));
                vp[j] = val;
            }
            *(float4*)&Cout[(size_t)row * M + col0] = v;
        }
    }
}

// ---------------- attention: one block per (window, head) ----------------
#define ATT_SMEM (3 * 256 * 65 * 4)
__global__ void __launch_bounds__(256) attn_kernel() {
    extern __shared__ float smem[];
    float* qs = smem;               // [256][65]
    float* ks = smem + 256 * 65;
    float* vs = smem + 2 * 256 * 65;

    int p = blockIdx.x, head = blockIdx.y;
    int tid = threadIdx.x;

    const float* Qb = g_q + (size_t)p * 256 * CD + head * DHEAD;
    const float* Kb = g_k + (size_t)p * 256 * CD + head * DHEAD;
    const float* Vb = g_v + (size_t)p * 256 * CD + head * DHEAD;

    for (int i = tid; i < 256 * 64; i += 256) {
        int r = i >> 6, d = i & 63;
        qs[r * 65 + d] = Qb[(size_t)r * CD + d];
        ks[r * 65 + d] = Kb[(size_t)r * CD + d];
        vs[r * 65 + d] = Vb[(size_t)r * CD + d];
    }
    __syncthreads();

    float q[64], acc[64];
    #pragma unroll
    for (int d = 0; d < 64; d++) { q[d] = qs[tid * 65 + d]; acc[d] = 0.f; }

    float m = -1e30f, l = 0.f;
    for (int j = 0; j < 256; j++) {
        const float* kr = ks + j * 65;
        float s0 = 0.f, s1 = 0.f, s2 = 0.f, s3 = 0.f;
        #pragma unroll
        for (int d = 0; d < 64; d += 4) {
            s0 += q[d    ] * kr[d    ];
            s1 += q[d + 1] * kr[d + 1];
            s2 += q[d + 2] * kr[d + 2];
            s3 += q[d + 3] * kr[d + 3];
        }
        float s = ((s0 + s1) + (s2 + s3)) * 0.125f;  // / sqrt(64)
        if (s > m) {
            float corr = __expf(m - s);
            l *= corr;
            #pragma unroll
            for (int d = 0; d < 64; d++) acc[d] *= corr;
            m = s;
        }
        float pw = __expf(s - m);
        l += pw;
        const float* vr = vs + j * 65;
        #pragma unroll
        for (int d = 0; d < 64; d++) acc[d] += pw * vr[d];
    }

    float inv = 1.f / l;
    float* Ob = g_att + ((size_t)p * 256 + tid) * CD + head * DHEAD;
    #pragma unroll
    for (int d = 0; d < 64; d++) Ob[d] = acc[d] * inv;
}

// ---------------- scatter (reverse window partition + reverse shift) ----------------
__global__ void scatter_kernel(float* __restrict__ out) {
    int n = blockIdx.x;
    int c = threadIdx.x;
    int p = n >> 8, t = n & 255;
    int bd = p >> 6, bh = (p >> 3) & 7, bw = p & 7;
    int td = t >> 6, th = (t >> 3) & 7, tw = t & 7;
    int od = (bd * 4 + td + 2) & 15;
    int oh = (bh * 8 + th + 4) & 63;
    int ow = (bw * 8 + tw + 4) & 63;
    int sp = od * HW + oh * 64 + ow;
    out[c * DHW + sp] = g_y[n * CD + c];
}

// ---------------- host launch ----------------
extern "C" void kernel_launch(void* const* d_in, const int* in_sizes, int n_in,
                              void* d_out, int out_size) {
    const float* x     = (const float*)d_in[0];
    const float* Wq    = (const float*)d_in[1];
    const float* bq    = (const float*)d_in[2];
    const float* Wk    = (const float*)d_in[3];
    const float* bk    = (const float*)d_in[4];
    const float* Wv    = (const float*)d_in[5];
    const float* bv    = (const float*)d_in[6];
    const float* Wo    = (const float*)d_in[7];
    const float* bo    = (const float*)d_in[8];
    const float* ln1_g = (const float*)d_in[9];
    const float* ln1_b = (const float*)d_in[10];
    const float* ln2_g = (const float*)d_in[11];
    const float* ln2_b = (const float*)d_in[12];
    const float* W1    = (const float*)d_in[13];
    const float* b1    = (const float*)d_in[14];
    const float* W2    = (const float*)d_in[15];
    const float* b2    = (const float*)d_in[16];
    float* out = (float*)d_out;

    float *p_xw, *p_h, *p_q, *p_k, *p_v, *p_att, *p_xw2, *p_h2, *p_hid, *p_y;
    cudaGetSymbolAddress((void**)&p_xw,  g_xw);
    cudaGetSymbolAddress((void**)&p_h,   g_h);
    cudaGetSymbolAddress((void**)&p_q,   g_q);
    cudaGetSymbolAddress((void**)&p_k,   g_k);
    cudaGetSymbolAddress((void**)&p_v,   g_v);
    cudaGetSymbolAddress((void**)&p_att, g_att);
    cudaGetSymbolAddress((void**)&p_xw2, g_xw2);
    cudaGetSymbolAddress((void**)&p_h2,  g_h2);
    cudaGetSymbolAddress((void**)&p_hid, g_hid);
    cudaGetSymbolAddress((void**)&p_y,   g_y);

    cudaFuncSetAttribute(attn_kernel, cudaFuncAttributeMaxDynamicSharedMemorySize, ATT_SMEM);

    // 1) gather + LN1
    gather_ln1_kernel<<<NTOK, 384>>>(x, ln1_g, ln1_b);

    // 2) QKV projections
    dim3 gC(512, 3);
    gemm_kernel<0><<<gC, 256>>>(p_h, Wq, bq, nullptr, p_q, 384, 384);
    gemm_kernel<0><<<gC, 256>>>(p_h, Wk, bk, nullptr, p_k, 384, 384);
    gemm_kernel<0><<<gC, 256>>>(p_h, Wv, bv, nullptr, p_v, 384, 384);

    // 3) attention
    attn_kernel<<<dim3(NWIN, NHEADS), 256, ATT_SMEM>>>();

    // 4) output projection + residual
    gemm_kernel<1><<<gC, 256>>>(p_att, Wo, bo, p_xw, p_xw2, 384, 384);

    // 5) LN2
    ln2_kernel<<<NTOK, 384>>>(ln2_g, ln2_b);

    // 6) MLP
    gemm_kernel<2><<<dim3(512, 12), 256>>>(p_h2, W1, b1, nullptr, p_hid, 384, 1536);
    gemm_kernel<1><<<gC, 256>>>(p_hid, W2, b2, p_xw2, p_y, 1536, 384);

    // 7) scatter back
    scatter_kernel<<<NTOK, 384>>>(out);
}

// round 3
// speedup vs baseline: 1.9956x; 1.9956x over previous
#include <cuda_runtime.h>
#include <math.h>
#include <cstdint>

// Problem constants
#define CD   384
#define TWIN 256
#define NWIN 256
#define NTOK 65536
#define NHEADS 6
#define DHEAD 64
#define MLPD 1536
#define DHW 65536
#define HW 4096
#define QKVD 1152

// -------- scratch (device globals; allocation-free contract) --------
__device__ float g_xw [NTOK * CD];           // gathered windows (residual 1)
__device__ float g_h  [NTOK * CD];           // LN1 output
__device__ float g_qkv[(size_t)NTOK * QKVD]; // fused QKV
__device__ float g_att[NTOK * CD];           // attention output
__device__ float g_xw2[NTOK * CD];           // after O-proj residual (residual 2)
__device__ float g_h2 [NTOK * CD];           // LN2 output
__device__ float g_hid[(size_t)NTOK * MLPD]; // MLP hidden
__device__ float g_y  [NTOK * CD];           // final window-space output
// transposed weights (K-major rows: row = output feature)
__device__ float g_wqkvT[QKVD * CD];
__device__ float g_woT  [CD * CD];
__device__ float g_w1T  [MLPD * CD];
__device__ float g_w2T  [CD * MLPD];
__device__ float g_bqkv [QKVD];

// ---- tf32 helpers ----
__device__ __forceinline__ uint32_t f2tf32(float x) {
    uint32_t u;
    asm("cvt.rna.tf32.f32 %0, %1;" : "=r"(u) : "f"(x));
    return u;
}
__device__ __forceinline__ void mma_tf32(float* c, const uint32_t* a, const uint32_t* b) {
    asm volatile(
        "mma.sync.aligned.m16n8k8.row.col.f32.tf32.tf32.f32 "
        "{%0,%1,%2,%3}, {%4,%5,%6,%7}, {%8,%9}, {%0,%1,%2,%3};"
        : "+f"(c[0]), "+f"(c[1]), "+f"(c[2]), "+f"(c[3])
        : "r"(a[0]), "r"(a[1]), "r"(a[2]), "r"(a[3]), "r"(b[0]), "r"(b[1]));
}

// ================= tensor-core tf32 GEMM (mma.sync) =================
// C[128,128] tile = A[N,K] @ BT[M,K]^T.  BT rows = output features (K-major).
// 256 threads = 8 warps; warp tile 64x32 (wm = wid&1, wn = wid>>2? no: wid>>1).
// Smem fragment-ordered:
//   A atoms: [m-atom(8)][q(4)] each 128 floats laid out [lane][i]  -> LDS.128
//   B atoms: [n-atom(16)][q(4)] each 64 floats laid out [lane][i]  -> LDS.64
// MODE 0: +bias    MODE 1: +bias+res    MODE 2: gelu(+bias)
template<int MODE>
__global__ void __launch_bounds__(256)
tgemm_kernel(const float* __restrict__ A, const float* __restrict__ BT,
             const float* __restrict__ bias, const float* __restrict__ res,
             float* __restrict__ Cout, int K, int Mtot) {
    __shared__ uint32_t sA[4096];   // 16 KB
    __shared__ uint32_t sB[4096];   // 16 KB

    const int tid  = threadIdx.x;
    const int wid  = tid >> 5;
    const int lane = tid & 31;
    const int wm   = wid & 1;       // 0..1 : which 64-row half
    const int wn   = wid >> 1;      // 0..3 : which 32-col quarter
    const int brow = blockIdx.x * 128;
    const int bcol = blockIdx.y * 128;

    // global-load mapping: idx = tid + 256*j ; r = idx>>3 (0..127), g = idx&7
    const int r_ld = tid >> 3;      // base row (stride 32 per j)
    const int g_ld = tid & 7;       // float4 group within 32-wide K chunk

    const float* Ap = A  + (size_t)(brow + r_ld) * K + g_ld * 4;
    const float* Bp = BT + (size_t)(bcol + r_ld) * K + g_ld * 4;

    float acc[64];
    #pragma unroll
    for (int i = 0; i < 64; i++) acc[i] = 0.f;

    const int nk = K >> 5;
    float4 pa[4], pb[4];

    // prefetch chunk 0
    #pragma unroll
    for (int j = 0; j < 4; j++) {
        pa[j] = *(const float4*)(Ap + (size_t)(32 * j) * K);
        pb[j] = *(const float4*)(Bp + (size_t)(32 * j) * K);
    }

    for (int c = 0; c < nk; c++) {
        __syncthreads();   // previous compute done before overwrite
        // fragment-ordered stores (tf32-rounded)
        #pragma unroll
        for (int j = 0; j < 4; j++) {
            int r = r_ld + 32 * j;          // 0..127
            // A: atom = (r>>4)*4 + (g>>1); i = ((r>>3)&1) + 2*(g&1); L = (r&7)*4 + c4
            {
                int atom = ((r >> 4) * 4 + (g_ld >> 1)) << 7;
                int ii   = ((r >> 3) & 1) + 2 * (g_ld & 1);
                int Lb   = (r & 7) * 4;
                const float* e = &pa[j].x;
                #pragma unroll
                for (int c4 = 0; c4 < 4; c4++)
                    sA[atom + (Lb + c4) * 4 + ii] = f2tf32(e[c4]);
            }
            // B: atom = (n>>3)*4 + (g>>1); i = g&1; L = (n&7)*4 + c4
            {
                int atom = ((r >> 3) * 4 + (g_ld >> 1)) << 6;
                int ii   = g_ld & 1;
                int Lb   = (r & 7) * 4;
                const float* e = &pb[j].x;
                #pragma unroll
                for (int c4 = 0; c4 < 4; c4++)
                    sB[atom + (Lb + c4) * 2 + ii] = f2tf32(e[c4]);
            }
        }
        // prefetch next chunk
        if (c + 1 < nk) {
            #pragma unroll
            for (int j = 0; j < 4; j++) {
                pa[j] = *(const float4*)(Ap + (size_t)(32 * j) * K + (c + 1) * 32);
                pb[j] = *(const float4*)(Bp + (size_t)(32 * j) * K + (c + 1) * 32);
            }
        }
        __syncthreads();

        // compute 4 k8-steps
        #pragma unroll
        for (int q = 0; q < 4; q++) {
            uint32_t af[4][4];
            uint32_t bf[4][2];
            #pragma unroll
            for (int am = 0; am < 4; am++) {
                const uint4 v = *(const uint4*)&sA[((((wm * 4 + am) * 4 + q)) << 7) + lane * 4];
                af[am][0] = v.x; af[am][1] = v.y; af[am][2] = v.z; af[am][3] = v.w;
            }
            #pragma unroll
            for (int bn = 0; bn < 4; bn++) {
                const uint2 v = *(const uint2*)&sB[((((wn * 4 + bn) * 4 + q)) << 6) + lane * 2];
                bf[bn][0] = v.x; bf[bn][1] = v.y;
            }
            #pragma unroll
            for (int am = 0; am < 4; am++)
                #pragma unroll
                for (int bn = 0; bn < 4; bn++)
                    mma_tf32(&acc[(am * 4 + bn) * 4], af[am], bf[bn]);
        }
    }

    // epilogue
    #pragma unroll
    for (int am = 0; am < 4; am++) {
        int row0 = brow + wm * 64 + am * 16 + (lane >> 2);
        #pragma unroll
        for (int bn = 0; bn < 4; bn++) {
            int col = bcol + wn * 32 + bn * 8 + 2 * (lane & 3);
            float2 bv = *(const float2*)(bias + col);
            const int ix = (am * 4 + bn) * 4;
            float2 o0 = make_float2(acc[ix + 0] + bv.x, acc[ix + 1] + bv.y);
            float2 o1 = make_float2(acc[ix + 2] + bv.x, acc[ix + 3] + bv.y);
            if (MODE == 1) {
                float2 r0 = *(const float2*)(res + (size_t)row0 * Mtot + col);
                float2 r1 = *(const float2*)(res + (size_t)(row0 + 8) * Mtot + col);
                o0.x += r0.x; o0.y += r0.y; o1.x += r1.x; o1.y += r1.y;
            }
            if (MODE == 2) {
                o0.x = 0.5f * o0.x * (1.0f + erff(o0.x * 0.7071067811865476f));
                o0.y = 0.5f * o0.y * (1.0f + erff(o0.y * 0.7071067811865476f));
                o1.x = 0.5f * o1.x * (1.0f + erff(o1.x * 0.7071067811865476f));
                o1.y = 0.5f * o1.y * (1.0f + erff(o1.y * 0.7071067811865476f));
            }
            *(float2*)(Cout + (size_t)row0 * Mtot + col) = o0;
            *(float2*)(Cout + (size_t)(row0 + 8) * Mtot + col) = o1;
        }
    }
}

// ================= weight transpose =================
__global__ void transpose_kernel(const float* __restrict__ W, float* __restrict__ WT,
                                 int R, int Cc) {
    __shared__ float t[32][33];
    int r0 = blockIdx.y * 32, c0 = blockIdx.x * 32;
    int x = threadIdx.x, y = threadIdx.y;
    #pragma unroll
    for (int i = y; i < 32; i += 8) t[i][x] = W[(size_t)(r0 + i) * Cc + c0 + x];
    __syncthreads();
    #pragma unroll
    for (int i = y; i < 32; i += 8) WT[(size_t)(c0 + i) * R + r0 + x] = t[x][i];
}

__global__ void bias_concat_kernel(const float* bq, const float* bk, const float* bv) {
    int i = threadIdx.x + blockIdx.x * blockDim.x;
    if (i < 384) g_bqkv[i] = bq[i];
    else if (i < 768) g_bqkv[i] = bk[i - 384];
    else if (i < 1152) g_bqkv[i] = bv[i - 768];
}

// ================= gather + LN1 =================
__global__ void gather_ln1_kernel(const float* __restrict__ x,
                                  const float* __restrict__ gamma,
                                  const float* __restrict__ beta) {
    int n = blockIdx.x;
    int c = threadIdx.x;
    int p = n >> 8, t = n & 255;
    int bd = p >> 6, bh = (p >> 3) & 7, bw = p & 7;
    int td = t >> 6, th = (t >> 3) & 7, tw = t & 7;
    int od = (bd * 4 + td + 2) & 15;
    int oh = (bh * 8 + th + 4) & 63;
    int ow = (bw * 8 + tw + 4) & 63;
    int sp = od * HW + oh * 64 + ow;

    float val = x[c * DHW + sp];

    __shared__ float red[12];
    __shared__ float mu_s, rs_s;
    float s = val;
    #pragma unroll
    for (int o = 16; o; o >>= 1) s += __shfl_down_sync(0xffffffffu, s, o);
    if ((threadIdx.x & 31) == 0) red[threadIdx.x >> 5] = s;
    __syncthreads();
    if (threadIdx.x < 32) {
        float ts = (threadIdx.x < 12) ? red[threadIdx.x] : 0.f;
        #pragma unroll
        for (int o = 8; o; o >>= 1) ts += __shfl_down_sync(0xffffffffu, ts, o);
        if (threadIdx.x == 0) mu_s = ts * (1.f / 384.f);
    }
    __syncthreads();
    float d = val - mu_s;
    float s2 = d * d;
    #pragma unroll
    for (int o = 16; o; o >>= 1) s2 += __shfl_down_sync(0xffffffffu, s2, o);
    if ((threadIdx.x & 31) == 0) red[threadIdx.x >> 5] = s2;
    __syncthreads();
    if (threadIdx.x < 32) {
        float ts = (threadIdx.x < 12) ? red[threadIdx.x] : 0.f;
        #pragma unroll
        for (int o = 8; o; o >>= 1) ts += __shfl_down_sync(0xffffffffu, ts, o);
        if (threadIdx.x == 0) rs_s = rsqrtf(ts * (1.f / 384.f) + 1e-5f);
    }
    __syncthreads();
    g_xw[n * CD + c] = val;
    g_h [n * CD + c] = d * rs_s * gamma[c] + beta[c];
}

// ================= LN2 =================
__global__ void ln2_kernel(const float* __restrict__ gamma,
                           const float* __restrict__ beta) {
    int n = blockIdx.x;
    int c = threadIdx.x;
    float val = g_xw2[n * CD + c];
    __shared__ float red[12];
    __shared__ float mu_s, rs_s;
    float s = val;
    #pragma unroll
    for (int o = 16; o; o >>= 1) s += __shfl_down_sync(0xffffffffu, s, o);
    if ((threadIdx.x & 31) == 0) red[threadIdx.x >> 5] = s;
    __syncthreads();
    if (threadIdx.x < 32) {
        float ts = (threadIdx.x < 12) ? red[threadIdx.x] : 0.f;
        #pragma unroll
        for (int o = 8; o; o >>= 1) ts += __shfl_down_sync(0xffffffffu, ts, o);
        if (threadIdx.x == 0) mu_s = ts * (1.f / 384.f);
    }
    __syncthreads();
    float d = val - mu_s;
    float s2 = d * d;
    #pragma unroll
    for (int o = 16; o; o >>= 1) s2 += __shfl_down_sync(0xffffffffu, s2, o);
    if ((threadIdx.x & 31) == 0) red[threadIdx.x >> 5] = s2;
    __syncthreads();
    if (threadIdx.x < 32) {
        float ts = (threadIdx.x < 12) ? red[threadIdx.x] : 0.f;
        #pragma unroll
        for (int o = 8; o; o >>= 1) ts += __shfl_down_sync(0xffffffffu, ts, o);
        if (threadIdx.x == 0) rs_s = rsqrtf(ts * (1.f / 384.f) + 1e-5f);
    }
    __syncthreads();
    g_h2[n * CD + c] = d * rs_s * gamma[c] + beta[c];
}

// ================= attention =================
#define ATT_STR 72   // padded row stride (floats), 16B aligned
#define ATT_SMEM (3 * 256 * ATT_STR * 4)
__global__ void __launch_bounds__(256) attn_kernel() {
    extern __shared__ float smf[];
    float* qs = smf;
    float* ks = smf + 256 * ATT_STR;
    float* vs = smf + 2 * 256 * ATT_STR;

    int p = blockIdx.x, head = blockIdx.y;
    int tid = threadIdx.x;

    const float4* Qb = (const float4*)(g_qkv + (size_t)p * 256 * QKVD + head * DHEAD);
    const float4* Kb = (const float4*)(g_qkv + (size_t)p * 256 * QKVD + 384 + head * DHEAD);
    const float4* Vb = (const float4*)(g_qkv + (size_t)p * 256 * QKVD + 768 + head * DHEAD);

    for (int i = tid; i < 256 * 16; i += 256) {
        int r = i >> 4, d4 = i & 15;
        ((float4*)(qs + r * ATT_STR))[d4] = Qb[(size_t)r * (QKVD / 4) + d4];
        ((float4*)(ks + r * ATT_STR))[d4] = Kb[(size_t)r * (QKVD / 4) + d4];
        ((float4*)(vs + r * ATT_STR))[d4] = Vb[(size_t)r * (QKVD / 4) + d4];
    }
    __syncthreads();

    float4 q4[16], a4[16];
    #pragma unroll
    for (int d = 0; d < 16; d++) {
        q4[d] = ((const float4*)(qs + tid * ATT_STR))[d];
        a4[d] = make_float4(0.f, 0.f, 0.f, 0.f);
    }

    float m = -1e30f, l = 0.f;
    for (int j = 0; j < 256; j++) {
        const float4* kr = (const float4*)(ks + j * ATT_STR);
        float s0 = 0.f, s1 = 0.f, s2 = 0.f, s3 = 0.f;
        #pragma unroll
        for (int d = 0; d < 16; d++) {
            float4 kv = kr[d];
            s0 += q4[d].x * kv.x; s1 += q4[d].y * kv.y;
            s2 += q4[d].z * kv.z; s3 += q4[d].w * kv.w;
        }
        float s = ((s0 + s1) + (s2 + s3)) * 0.125f;
        if (s > m) {
            float corr = __expf(m - s);
            l *= corr;
            #pragma unroll
            for (int d = 0; d < 16; d++) {
                a4[d].x *= corr; a4[d].y *= corr; a4[d].z *= corr; a4[d].w *= corr;
            }
            m = s;
        }
        float pw = __expf(s - m);
        l += pw;
        const float4* vr = (const float4*)(vs + j * ATT_STR);
        #pragma unroll
        for (int d = 0; d < 16; d++) {
            float4 vv = vr[d];
            a4[d].x += pw * vv.x; a4[d].y += pw * vv.y;
            a4[d].z += pw * vv.z; a4[d].w += pw * vv.w;
        }
    }
    float inv = 1.f / l;
    float4* Ob = (float4*)(g_att + ((size_t)p * 256 + tid) * CD + head * DHEAD);
    #pragma unroll
    for (int d = 0; d < 16; d++) {
        float4 o = a4[d];
        o.x *= inv; o.y *= inv; o.z *= inv; o.w *= inv;
        Ob[d] = o;
    }
}

// ================= scatter =================
__global__ void scatter_kernel(float* __restrict__ out) {
    int n = blockIdx.x;
    int c = threadIdx.x;
    int p = n >> 8, t = n & 255;
    int bd = p >> 6, bh = (p >> 3) & 7, bw = p & 7;
    int td = t >> 6, th = (t >> 3) & 7, tw = t & 7;
    int od = (bd * 4 + td + 2) & 15;
    int oh = (bh * 8 + th + 4) & 63;
    int ow = (bw * 8 + tw + 4) & 63;
    int sp = od * HW + oh * 64 + ow;
    out[c * DHW + sp] = g_y[n * CD + c];
}

// ================= host launch =================
extern "C" void kernel_launch(void* const* d_in, const int* in_sizes, int n_in,
                              void* d_out, int out_size) {
    const float* x     = (const float*)d_in[0];
    const float* Wq    = (const float*)d_in[1];
    const float* bq    = (const float*)d_in[2];
    const float* Wk    = (const float*)d_in[3];
    const float* bk    = (const float*)d_in[4];
    const float* Wv    = (const float*)d_in[5];
    const float* bv    = (const float*)d_in[6];
    const float* Wo    = (const float*)d_in[7];
    const float* bo    = (const float*)d_in[8];
    const float* ln1_g = (const float*)d_in[9];
    const float* ln1_b = (const float*)d_in[10];
    const float* ln2_g = (const float*)d_in[11];
    const float* ln2_b = (const float*)d_in[12];
    const float* W1    = (const float*)d_in[13];
    const float* b1    = (const float*)d_in[14];
    const float* W2    = (const float*)d_in[15];
    const float* b2    = (const float*)d_in[16];
    float* out = (float*)d_out;

    float *p_h, *p_qkv, *p_att, *p_xw, *p_xw2, *p_h2, *p_hid, *p_y;
    float *p_wqkvT, *p_woT, *p_w1T, *p_w2T, *p_bqkv;
    cudaGetSymbolAddress((void**)&p_h,    g_h);
    cudaGetSymbolAddress((void**)&p_qkv,  g_qkv);
    cudaGetSymbolAddress((void**)&p_att,  g_att);
    cudaGetSymbolAddress((void**)&p_xw,   g_xw);
    cudaGetSymbolAddress((void**)&p_xw2,  g_xw2);
    cudaGetSymbolAddress((void**)&p_h2,   g_h2);
    cudaGetSymbolAddress((void**)&p_hid,  g_hid);
    cudaGetSymbolAddress((void**)&p_y,    g_y);
    cudaGetSymbolAddress((void**)&p_wqkvT, g_wqkvT);
    cudaGetSymbolAddress((void**)&p_woT,  g_woT);
    cudaGetSymbolAddress((void**)&p_w1T,  g_w1T);
    cudaGetSymbolAddress((void**)&p_w2T,  g_w2T);
    cudaGetSymbolAddress((void**)&p_bqkv, g_bqkv);

    cudaFuncSetAttribute(attn_kernel, cudaFuncAttributeMaxDynamicSharedMemorySize, ATT_SMEM);

    dim3 tb(32, 8);
    // 0) weight transposes + bias concat
    transpose_kernel<<<dim3(12, 12), tb>>>(Wq, p_wqkvT,             384, 384);
    transpose_kernel<<<dim3(12, 12), tb>>>(Wk, p_wqkvT + 384 * 384, 384, 384);
    transpose_kernel<<<dim3(12, 12), tb>>>(Wv, p_wqkvT + 768 * 384, 384, 384);
    transpose_kernel<<<dim3(12, 12), tb>>>(Wo, p_woT,               384, 384);
    transpose_kernel<<<dim3(48, 12), tb>>>(W1, p_w1T,               384, 1536);
    transpose_kernel<<<dim3(12, 48), tb>>>(W2, p_w2T,               1536, 384);
    bias_concat_kernel<<<3, 384>>>(bq, bk, bv);

    // 1) gather + LN1
    gather_ln1_kernel<<<NTOK, 384>>>(x, ln1_g, ln1_b);

    // 2) fused QKV projection (tensor core tf32)
    tgemm_kernel<0><<<dim3(512, 9), 256>>>(p_h, p_wqkvT, p_bqkv, nullptr, p_qkv, 384, QKVD);

    // 3) attention
    attn_kernel<<<dim3(NWIN, NHEADS), 256, ATT_SMEM>>>();

    // 4) output projection + residual
    tgemm_kernel<1><<<dim3(512, 3), 256>>>(p_att, p_woT, bo, p_xw, p_xw2, 384, 384);

    // 5) LN2
    ln2_kernel<<<NTOK, 384>>>(ln2_g, ln2_b);

    // 6) MLP
    tgemm_kernel<2><<<dim3(512, 12), 256>>>(p_h2, p_w1T, b1, nullptr, p_hid, 384, 1536);
    tgemm_kernel<1><<<dim3(512, 3), 256>>>(p_hid, p_w2T, b2, p_xw2, p_y, 1536, 384);

    // 7) scatter back
    scatter_kernel<<<NTOK, 384>>>(out);
}

// round 4
// speedup vs baseline: 2.5647x; 1.2852x over previous
#include <cuda_runtime.h>
#include <math.h>
#include <cstdint>

// Problem constants
#define CD   384
#define TWIN 256
#define NWIN 256
#define NTOK 65536
#define NHEADS 6
#define DHEAD 64
#define MLPD 1536
#define DHW 65536
#define HW 4096
#define QKVD 1152

// -------- scratch (device globals; allocation-free contract) --------
__device__ float g_xw [NTOK * CD];
__device__ float g_h  [NTOK * CD];
__device__ float g_qkv[(size_t)NTOK * QKVD];
__device__ float g_att[NTOK * CD];
__device__ float g_xw2[NTOK * CD];
__device__ float g_h2 [NTOK * CD];
__device__ float g_hid[(size_t)NTOK * MLPD];
__device__ float g_y  [NTOK * CD];
__device__ float g_wqkvT[QKVD * CD];
__device__ float g_woT  [CD * CD];
__device__ float g_w1T  [MLPD * CD];
__device__ float g_w2T  [CD * MLPD];
__device__ float g_bqkv [QKVD];

// ---- tf32 helpers ----
__device__ __forceinline__ uint32_t f2tf32(float x) {
    uint32_t u;
    asm("cvt.rna.tf32.f32 %0, %1;" : "=r"(u) : "f"(x));
    return u;
}
__device__ __forceinline__ void mma_tf32(float* c, const uint32_t* a, const uint32_t* b) {
    asm volatile(
        "mma.sync.aligned.m16n8k8.row.col.f32.tf32.tf32.f32 "
        "{%0,%1,%2,%3}, {%4,%5,%6,%7}, {%8,%9}, {%0,%1,%2,%3};"
        : "+f"(c[0]), "+f"(c[1]), "+f"(c[2]), "+f"(c[3])
        : "r"(a[0]), "r"(a[1]), "r"(a[2]), "r"(a[3]), "r"(b[0]), "r"(b[1]));
}

// ================= tensor-core tf32 GEMM (mma.sync) =================
template<int MODE>
__global__ void __launch_bounds__(256)
tgemm_kernel(const float* __restrict__ A, const float* __restrict__ BT,
             const float* __restrict__ bias, const float* __restrict__ res,
             float* __restrict__ Cout, int K, int Mtot) {
    __shared__ uint32_t sA[4096];
    __shared__ uint32_t sB[4096];

    const int tid  = threadIdx.x;
    const int wid  = tid >> 5;
    const int lane = tid & 31;
    const int wm   = wid & 1;
    const int wn   = wid >> 1;
    const int brow = blockIdx.x * 128;
    const int bcol = blockIdx.y * 128;

    const int r_ld = tid >> 3;
    const int g_ld = tid & 7;

    const float* Ap = A  + (size_t)(brow + r_ld) * K + g_ld * 4;
    const float* Bp = BT + (size_t)(bcol + r_ld) * K + g_ld * 4;

    float acc[64];
    #pragma unroll
    for (int i = 0; i < 64; i++) acc[i] = 0.f;

    const int nk = K >> 5;
    float4 pa[4], pb[4];

    #pragma unroll
    for (int j = 0; j < 4; j++) {
        pa[j] = *(const float4*)(Ap + (size_t)(32 * j) * K);
        pb[j] = *(const float4*)(Bp + (size_t)(32 * j) * K);
    }

    for (int c = 0; c < nk; c++) {
        __syncthreads();
        #pragma unroll
        for (int j = 0; j < 4; j++) {
            int r = r_ld + 32 * j;
            {
                int atom = ((r >> 4) * 4 + (g_ld >> 1)) << 7;
                int ii   = ((r >> 3) & 1) + 2 * (g_ld & 1);
                int Lb   = (r & 7) * 4;
                const float* e = &pa[j].x;
                #pragma unroll
                for (int c4 = 0; c4 < 4; c4++)
                    sA[atom + (Lb + c4) * 4 + ii] = f2tf32(e[c4]);
            }
            {
                int atom = ((r >> 3) * 4 + (g_ld >> 1)) << 6;
                int ii   = g_ld & 1;
                int Lb   = (r & 7) * 4;
                const float* e = &pb[j].x;
                #pragma unroll
                for (int c4 = 0; c4 < 4; c4++)
                    sB[atom + (Lb + c4) * 2 + ii] = f2tf32(e[c4]);
            }
        }
        if (c + 1 < nk) {
            #pragma unroll
            for (int j = 0; j < 4; j++) {
                pa[j] = *(const float4*)(Ap + (size_t)(32 * j) * K + (c + 1) * 32);
                pb[j] = *(const float4*)(Bp + (size_t)(32 * j) * K + (c + 1) * 32);
            }
        }
        __syncthreads();

        #pragma unroll
        for (int q = 0; q < 4; q++) {
            uint32_t af[4][4];
            uint32_t bf[4][2];
            #pragma unroll
            for (int am = 0; am < 4; am++) {
                const uint4 v = *(const uint4*)&sA[((((wm * 4 + am) * 4 + q)) << 7) + lane * 4];
                af[am][0] = v.x; af[am][1] = v.y; af[am][2] = v.z; af[am][3] = v.w;
            }
            #pragma unroll
            for (int bn = 0; bn < 4; bn++) {
                const uint2 v = *(const uint2*)&sB[((((wn * 4 + bn) * 4 + q)) << 6) + lane * 2];
                bf[bn][0] = v.x; bf[bn][1] = v.y;
            }
            #pragma unroll
            for (int am = 0; am < 4; am++)
                #pragma unroll
                for (int bn = 0; bn < 4; bn++)
                    mma_tf32(&acc[(am * 4 + bn) * 4], af[am], bf[bn]);
        }
    }

    #pragma unroll
    for (int am = 0; am < 4; am++) {
        int row0 = brow + wm * 64 + am * 16 + (lane >> 2);
        #pragma unroll
        for (int bn = 0; bn < 4; bn++) {
            int col = bcol + wn * 32 + bn * 8 + 2 * (lane & 3);
            float2 bv = *(const float2*)(bias + col);
            const int ix = (am * 4 + bn) * 4;
            float2 o0 = make_float2(acc[ix + 0] + bv.x, acc[ix + 1] + bv.y);
            float2 o1 = make_float2(acc[ix + 2] + bv.x, acc[ix + 3] + bv.y);
            if (MODE == 1) {
                float2 r0 = *(const float2*)(res + (size_t)row0 * Mtot + col);
                float2 r1 = *(const float2*)(res + (size_t)(row0 + 8) * Mtot + col);
                o0.x += r0.x; o0.y += r0.y; o1.x += r1.x; o1.y += r1.y;
            }
            if (MODE == 2) {
                o0.x = 0.5f * o0.x * (1.0f + erff(o0.x * 0.7071067811865476f));
                o0.y = 0.5f * o0.y * (1.0f + erff(o0.y * 0.7071067811865476f));
                o1.x = 0.5f * o1.x * (1.0f + erff(o1.x * 0.7071067811865476f));
                o1.y = 0.5f * o1.y * (1.0f + erff(o1.y * 0.7071067811865476f));
            }
            *(float2*)(Cout + (size_t)row0 * Mtot + col) = o0;
            *(float2*)(Cout + (size_t)(row0 + 8) * Mtot + col) = o1;
        }
    }
}

// ================= weight transpose =================
__global__ void transpose_kernel(const float* __restrict__ W, float* __restrict__ WT,
                                 int R, int Cc) {
    __shared__ float t[32][33];
    int r0 = blockIdx.y * 32, c0 = blockIdx.x * 32;
    int x = threadIdx.x, y = threadIdx.y;
    #pragma unroll
    for (int i = y; i < 32; i += 8) t[i][x] = W[(size_t)(r0 + i) * Cc + c0 + x];
    __syncthreads();
    #pragma unroll
    for (int i = y; i < 32; i += 8) WT[(size_t)(c0 + i) * R + r0 + x] = t[x][i];
}

__global__ void bias_concat_kernel(const float* bq, const float* bk, const float* bv) {
    int i = threadIdx.x + blockIdx.x * blockDim.x;
    if (i < 384) g_bqkv[i] = bq[i];
    else if (i < 768) g_bqkv[i] = bk[i - 384];
    else if (i < 1152) g_bqkv[i] = bv[i - 768];
}

// ================= gather (coalesced) + LN1 =================
// block = one 8-token w-run (fixed p, td, th; tw=0..7), 384 threads = channels
__global__ void __launch_bounds__(384) gather_ln1_kernel(const float* __restrict__ x,
                                  const float* __restrict__ gamma,
                                  const float* __restrict__ beta) {
    __shared__ float s[384 * 9];
    __shared__ float smu[8], srs[8];

    int run = blockIdx.x;
    int p = run >> 5, td = (run >> 3) & 3, th = run & 7;
    int bd = p >> 6, bh = (p >> 3) & 7, bw = p & 7;
    int od = (bd * 4 + td + 2) & 15;
    int oh = (bh * 8 + th + 4) & 63;
    int w0 = (bw * 8 + 4) & 63;
    int w1 = (bw * 8 + 8) & 63;
    int n0 = p * 256 + td * 64 + th * 8;

    int c = threadIdx.x;
    const float* base = x + (size_t)c * DHW + od * HW + oh * 64;
    float4 fa = *(const float4*)(base + w0);
    float4 fb = *(const float4*)(base + w1);
    s[c * 9 + 0] = fa.x; s[c * 9 + 1] = fa.y; s[c * 9 + 2] = fa.z; s[c * 9 + 3] = fa.w;
    s[c * 9 + 4] = fb.x; s[c * 9 + 5] = fb.y; s[c * 9 + 6] = fb.z; s[c * 9 + 7] = fb.w;
    __syncthreads();

    int wid = c >> 5, lane = c & 31;
    if (wid < 8) {
        float sum = 0.f, sq = 0.f;
        #pragma unroll
        for (int i = 0; i < 12; i++) {
            float v = s[(lane + 32 * i) * 9 + wid];
            sum += v; sq += v * v;
        }
        #pragma unroll
        for (int o = 16; o; o >>= 1) {
            sum += __shfl_xor_sync(0xffffffffu, sum, o);
            sq  += __shfl_xor_sync(0xffffffffu, sq, o);
        }
        if (lane == 0) {
            float mu = sum * (1.f / 384.f);
            float var = sq * (1.f / 384.f) - mu * mu;
            smu[wid] = mu;
            srs[wid] = rsqrtf(var + 1e-5f);
        }
    }
    __syncthreads();

    float g = gamma[c], b = beta[c];
    #pragma unroll
    for (int j = 0; j < 8; j++) {
        float val = s[c * 9 + j];
        g_xw[(size_t)(n0 + j) * CD + c] = val;
        g_h [(size_t)(n0 + j) * CD + c] = (val - smu[j]) * srs[j] * g + b;
    }
}

// ================= LN2 =================
__global__ void ln2_kernel(const float* __restrict__ gamma,
                           const float* __restrict__ beta) {
    int n = blockIdx.x;
    int c = threadIdx.x;
    float val = g_xw2[n * CD + c];
    __shared__ float red[12];
    __shared__ float mu_s, rs_s;
    float s = val;
    #pragma unroll
    for (int o = 16; o; o >>= 1) s += __shfl_down_sync(0xffffffffu, s, o);
    if ((threadIdx.x & 31) == 0) red[threadIdx.x >> 5] = s;
    __syncthreads();
    if (threadIdx.x < 32) {
        float ts = (threadIdx.x < 12) ? red[threadIdx.x] : 0.f;
        #pragma unroll
        for (int o = 8; o; o >>= 1) ts += __shfl_down_sync(0xffffffffu, ts, o);
        if (threadIdx.x == 0) mu_s = ts * (1.f / 384.f);
    }
    __syncthreads();
    float d = val - mu_s;
    float s2 = d * d;
    #pragma unroll
    for (int o = 16; o; o >>= 1) s2 += __shfl_down_sync(0xffffffffu, s2, o);
    if ((threadIdx.x & 31) == 0) red[threadIdx.x >> 5] = s2;
    __syncthreads();
    if (threadIdx.x < 32) {
        float ts = (threadIdx.x < 12) ? red[threadIdx.x] : 0.f;
        #pragma unroll
        for (int o = 8; o; o >>= 1) ts += __shfl_down_sync(0xffffffffu, ts, o);
        if (threadIdx.x == 0) rs_s = rsqrtf(ts * (1.f / 384.f) + 1e-5f);
    }
    __syncthreads();
    g_h2[n * CD + c] = d * rs_s * gamma[c] + beta[c];
}

// ================= tensor-core flash attention =================
// block = (window p, head h); 8 warps x 32 q-rows; KV blocks of 64.
#define AQ_STR 68
#define AK_STR 68
#define AV_STR 72
#define AP_STR 68
#define SQ_OFF 0
#define SK_OFF (256 * AQ_STR)                 // 17408
#define SV_OFF (SK_OFF + 64 * AK_STR)         // 21760
#define SP_OFF (SV_OFF + 64 * AV_STR)         // 26368
#define ATT_SMEM ((SP_OFF + 256 * AP_STR) * 4)  // 175104 B

__global__ void __launch_bounds__(256, 1) attn_tc_kernel() {
    extern __shared__ float sm[];
    float* sQ = sm + SQ_OFF;
    float* sK = sm + SK_OFF;
    float* sV = sm + SV_OFF;
    float* sP = sm + SP_OFF;

    const int p = blockIdx.x, h = blockIdx.y;
    const int tid = threadIdx.x;
    const int w = tid >> 5, lane = tid & 31;
    const int lq = lane >> 2, lr = lane & 3;

    // load Q: thread = row
    {
        const float* qrow = g_qkv + (size_t)(p * 256 + tid) * QKVD + h * 64;
        #pragma unroll
        for (int k = 0; k < 16; k++) {
            float4 v = *(const float4*)(qrow + 4 * k);
            uint4 u = make_uint4(f2tf32(v.x), f2tf32(v.y), f2tf32(v.z), f2tf32(v.w));
            *(uint4*)&sQ[tid * AQ_STR + 4 * k] = u;
        }
    }

    float oacc[64];
    #pragma unroll
    for (int i = 0; i < 64; i++) oacc[i] = 0.f;
    float mrow[4] = {-1e30f, -1e30f, -1e30f, -1e30f};
    float lrow[4] = {0.f, 0.f, 0.f, 0.f};

    for (int kb = 0; kb < 4; kb++) {
        __syncthreads();   // Q ready (first iter) / prev PV done (later)
        // load K,V block: 64 rows, thread handles (row=tid>>2, quarter=tid&3)
        {
            int r = tid >> 2, qt = tid & 3;
            const float* krow = g_qkv + (size_t)(p * 256 + kb * 64 + r) * QKVD + 384 + h * 64 + qt * 16;
            const float* vrow = krow + 384;
            #pragma unroll
            for (int e = 0; e < 4; e++) {
                float4 v = *(const float4*)(krow + 4 * e);
                *(uint4*)&sK[r * AK_STR + qt * 16 + 4 * e] =
                    make_uint4(f2tf32(v.x), f2tf32(v.y), f2tf32(v.z), f2tf32(v.w));
                float4 v2 = *(const float4*)(vrow + 4 * e);
                *(uint4*)&sV[r * AV_STR + qt * 16 + 4 * e] =
                    make_uint4(f2tf32(v2.x), f2tf32(v2.y), f2tf32(v2.z), f2tf32(v2.w));
            }
        }
        __syncthreads();

        // S = Q_warp(32x64) @ K_blk^T(64x64)
        float sacc[64];
        #pragma unroll
        for (int i = 0; i < 64; i++) sacc[i] = 0.f;
        #pragma unroll
        for (int q = 0; q < 8; q++) {
            uint32_t af[2][4];
            #pragma unroll
            for (int am = 0; am < 2; am++) {
                int R = 32 * w + 16 * am + lq;
                int col = lr + 8 * q;
                af[am][0] = __float_as_uint(sQ[R * AQ_STR + col]);
                af[am][1] = __float_as_uint(sQ[(R + 8) * AQ_STR + col]);
                af[am][2] = __float_as_uint(sQ[R * AQ_STR + col + 4]);
                af[am][3] = __float_as_uint(sQ[(R + 8) * AQ_STR + col + 4]);
            }
            uint32_t bf[8][2];
            #pragma unroll
            for (int bn = 0; bn < 8; bn++) {
                int key = 8 * bn + lq;
                bf[bn][0] = __float_as_uint(sK[key * AK_STR + lr + 8 * q]);
                bf[bn][1] = __float_as_uint(sK[key * AK_STR + lr + 4 + 8 * q]);
            }
            #pragma unroll
            for (int am = 0; am < 2; am++)
                #pragma unroll
                for (int bn = 0; bn < 8; bn++)
                    mma_tf32(&sacc[(am * 8 + bn) * 4], af[am], bf[bn]);
        }

        // online softmax per row-slot
        #pragma unroll
        for (int s = 0; s < 4; s++) {
            int am = s >> 1, hi = s & 1;
            float vmax = -1e30f;
            #pragma unroll
            for (int bn = 0; bn < 8; bn++) {
                float v0 = sacc[(am * 8 + bn) * 4 + 2 * hi] * 0.125f;
                float v1 = sacc[(am * 8 + bn) * 4 + 2 * hi + 1] * 0.125f;
                vmax = fmaxf(vmax, fmaxf(v0, v1));
            }
            vmax = fmaxf(vmax, __shfl_xor_sync(0xffffffffu, vmax, 1));
            vmax = fmaxf(vmax, __shfl_xor_sync(0xffffffffu, vmax, 2));
            float newm = fmaxf(mrow[s], vmax);
            float corr = __expf(mrow[s] - newm);
            mrow[s] = newm;
            float rsum = 0.f;
            int R = 32 * w + 16 * am + 8 * hi + lq;
            #pragma unroll
            for (int bn = 0; bn < 8; bn++) {
                float v0 = sacc[(am * 8 + bn) * 4 + 2 * hi] * 0.125f;
                float v1 = sacc[(am * 8 + bn) * 4 + 2 * hi + 1] * 0.125f;
                float p0 = __expf(v0 - newm), p1 = __expf(v1 - newm);
                rsum += p0 + p1;
                *(uint2*)&sP[R * AP_STR + 8 * bn + 2 * lr] = make_uint2(f2tf32(p0), f2tf32(p1));
            }
            rsum += __shfl_xor_sync(0xffffffffu, rsum, 1);
            rsum += __shfl_xor_sync(0xffffffffu, rsum, 2);
            lrow[s] = lrow[s] * corr + rsum;
            #pragma unroll
            for (int bn = 0; bn < 8; bn++) {
                oacc[(am * 8 + bn) * 4 + 2 * hi]     *= corr;
                oacc[(am * 8 + bn) * 4 + 2 * hi + 1] *= corr;
            }
        }
        __syncwarp();

        // O += P(32x64) @ V(64x64)
        #pragma unroll
        for (int q = 0; q < 8; q++) {
            uint32_t af[2][4];
            #pragma unroll
            for (int am = 0; am < 2; am++) {
                int R = 32 * w + 16 * am + lq;
                int col = lr + 8 * q;
                af[am][0] = __float_as_uint(sP[R * AP_STR + col]);
                af[am][1] = __float_as_uint(sP[(R + 8) * AP_STR + col]);
                af[am][2] = __float_as_uint(sP[R * AP_STR + col + 4]);
                af[am][3] = __float_as_uint(sP[(R + 8) * AP_STR + col + 4]);
            }
            uint32_t bf[8][2];
            #pragma unroll
            for (int bn = 0; bn < 8; bn++) {
                int d = 8 * bn + lq;
                bf[bn][0] = __float_as_uint(sV[(8 * q + lr) * AV_STR + d]);
                bf[bn][1] = __float_as_uint(sV[(8 * q + lr + 4) * AV_STR + d]);
            }
            #pragma unroll
            for (int am = 0; am < 2; am++)
                #pragma unroll
                for (int bn = 0; bn < 8; bn++)
                    mma_tf32(&oacc[(am * 8 + bn) * 4], af[am], bf[bn]);
        }
    }

    // epilogue: scale by 1/l, stage in sP (fp32), coalesced copy-out
    float inv[4];
    #pragma unroll
    for (int s = 0; s < 4; s++) inv[s] = 1.f / lrow[s];
    #pragma unroll
    for (int am = 0; am < 2; am++) {
        int R0 = 32 * w + 16 * am + lq;
        #pragma unroll
        for (int bn = 0; bn < 8; bn++) {
            const int ix = (am * 8 + bn) * 4;
            *(float2*)&sP[R0 * AP_STR + 8 * bn + 2 * lr] =
                make_float2(oacc[ix + 0] * inv[2 * am], oacc[ix + 1] * inv[2 * am]);
            *(float2*)&sP[(R0 + 8) * AP_STR + 8 * bn + 2 * lr] =
                make_float2(oacc[ix + 2] * inv[2 * am + 1], oacc[ix + 3] * inv[2 * am + 1]);
        }
    }
    __syncthreads();
    {
        float* orow = g_att + (size_t)(p * 256 + tid) * CD + h * 64;
        #pragma unroll
        for (int k = 0; k < 16; k++)
            *(float4*)(orow + 4 * k) = *(const float4*)&sP[tid * AP_STR + 4 * k];
    }
}

// ================= scatter (coalesced) =================
__global__ void __launch_bounds__(384) scatter_kernel(float* __restrict__ out) {
    int run = blockIdx.x;
    int p = run >> 5, td = (run >> 3) & 3, th = run & 7;
    int bd = p >> 6, bh = (p >> 3) & 7, bw = p & 7;
    int od = (bd * 4 + td + 2) & 15;
    int oh = (bh * 8 + th + 4) & 63;
    int w0 = (bw * 8 + 4) & 63;
    int w1 = (bw * 8 + 8) & 63;
    int n0 = p * 256 + td * 64 + th * 8;

    int c = threadIdx.x;
    float v[8];
    #pragma unroll
    for (int j = 0; j < 8; j++) v[j] = g_y[(size_t)(n0 + j) * CD + c];
    float* base = out + (size_t)c * DHW + od * HW + oh * 64;
    *(float4*)(base + w0) = make_float4(v[0], v[1], v[2], v[3]);
    *(float4*)(base + w1) = make_float4(v[4], v[5], v[6], v[7]);
}

// ================= host launch =================
extern "C" void kernel_launch(void* const* d_in, const int* in_sizes, int n_in,
                              void* d_out, int out_size) {
    const float* x     = (const float*)d_in[0];
    const float* Wq    = (const float*)d_in[1];
    const float* bq    = (const float*)d_in[2];
    const float* Wk    = (const float*)d_in[3];
    const float* bk    = (const float*)d_in[4];
    const float* Wv    = (const float*)d_in[5];
    const float* bv    = (const float*)d_in[6];
    const float* Wo    = (const float*)d_in[7];
    const float* bo    = (const float*)d_in[8];
    const float* ln1_g = (const float*)d_in[9];
    const float* ln1_b = (const float*)d_in[10];
    const float* ln2_g = (const float*)d_in[11];
    const float* ln2_b = (const float*)d_in[12];
    const float* W1    = (const float*)d_in[13];
    const float* b1    = (const float*)d_in[14];
    const float* W2    = (const float*)d_in[15];
    const float* b2    = (const float*)d_in[16];
    float* out = (float*)d_out;

    float *p_h, *p_qkv, *p_att, *p_xw, *p_xw2, *p_h2, *p_hid, *p_y;
    float *p_wqkvT, *p_woT, *p_w1T, *p_w2T, *p_bqkv;
    cudaGetSymbolAddress((void**)&p_h,    g_h);
    cudaGetSymbolAddress((void**)&p_qkv,  g_qkv);
    cudaGetSymbolAddress((void**)&p_att,  g_att);
    cudaGetSymbolAddress((void**)&p_xw,   g_xw);
    cudaGetSymbolAddress((void**)&p_xw2,  g_xw2);
    cudaGetSymbolAddress((void**)&p_h2,   g_h2);
    cudaGetSymbolAddress((void**)&p_hid,  g_hid);
    cudaGetSymbolAddress((void**)&p_y,    g_y);
    cudaGetSymbolAddress((void**)&p_wqkvT, g_wqkvT);
    cudaGetSymbolAddress((void**)&p_woT,  g_woT);
    cudaGetSymbolAddress((void**)&p_w1T,  g_w1T);
    cudaGetSymbolAddress((void**)&p_w2T,  g_w2T);
    cudaGetSymbolAddress((void**)&p_bqkv, g_bqkv);

    cudaFuncSetAttribute(attn_tc_kernel, cudaFuncAttributeMaxDynamicSharedMemorySize, ATT_SMEM);

    dim3 tb(32, 8);
    transpose_kernel<<<dim3(12, 12), tb>>>(Wq, p_wqkvT,             384, 384);
    transpose_kernel<<<dim3(12, 12), tb>>>(Wk, p_wqkvT + 384 * 384, 384, 384);
    transpose_kernel<<<dim3(12, 12), tb>>>(Wv, p_wqkvT + 768 * 384, 384, 384);
    transpose_kernel<<<dim3(12, 12), tb>>>(Wo, p_woT,               384, 384);
    transpose_kernel<<<dim3(48, 12), tb>>>(W1, p_w1T,               384, 1536);
    transpose_kernel<<<dim3(12, 48), tb>>>(W2, p_w2T,               1536, 384);
    bias_concat_kernel<<<3, 384>>>(bq, bk, bv);

    gather_ln1_kernel<<<8192, 384>>>(x, ln1_g, ln1_b);

    tgemm_kernel<0><<<dim3(512, 9), 256>>>(p_h, p_wqkvT, p_bqkv, nullptr, p_qkv, 384, QKVD);

    attn_tc_kernel<<<dim3(NWIN, NHEADS), 256, ATT_SMEM>>>();

    tgemm_kernel<1><<<dim3(512, 3), 256>>>(p_att, p_woT, bo, p_xw, p_xw2, 384, 384);

    ln2_kernel<<<NTOK, 384>>>(ln2_g, ln2_b);

    tgemm_kernel<2><<<dim3(512, 12), 256>>>(p_h2, p_w1T, b1, nullptr, p_hid, 384, 1536);
    tgemm_kernel<1><<<dim3(512, 3), 256>>>(p_hid, p_w2T, b2, p_xw2, p_y, 1536, 384);

    scatter_kernel<<<8192, 384>>>(out);
}

// round 10
// speedup vs baseline: 4.0849x; 1.5927x over previous
#include <cuda_runtime.h>
#include <math.h>
#include <cstdint>

// Problem constants
#define CD   384
#define TWIN 256
#define NWIN 256
#define NTOK 65536
#define NHEADS 6
#define DHEAD 64
#define MLPD 1536
#define DHW 65536
#define HW 4096
#define QKVD 1152

// -------- scratch (device globals; allocation-free contract) --------
__device__ float g_xw [NTOK * CD];
__device__ float g_h  [NTOK * CD];
__device__ float g_qkv[(size_t)NTOK * QKVD];
__device__ float g_att[NTOK * CD];
__device__ float g_xw2[NTOK * CD];
__device__ float g_h2 [NTOK * CD];
__device__ float g_hid[(size_t)NTOK * MLPD];
__device__ float g_y  [NTOK * CD];
__device__ float g_wqkv[CD * QKVD];   // [K=384][M=1152] concat of Wq|Wk|Wv columns
__device__ float g_bqkv[QKVD];

// ---- helpers ----
__device__ __forceinline__ uint32_t f2tf32(float x) {
    uint32_t u;
    asm("cvt.rna.tf32.f32 %0, %1;" : "=r"(u) : "f"(x));
    return u;
}
__device__ __forceinline__ void mma_tf32(float* c, const uint32_t* a, const uint32_t* b) {
    asm volatile(
        "mma.sync.aligned.m16n8k8.row.col.f32.tf32.tf32.f32 "
        "{%0,%1,%2,%3}, {%4,%5,%6,%7}, {%8,%9}, {%0,%1,%2,%3};"
        : "+f"(c[0]), "+f"(c[1]), "+f"(c[2]), "+f"(c[3])
        : "r"(a[0]), "r"(a[1]), "r"(a[2]), "r"(a[3]), "r"(b[0]), "r"(b[1]));
}
__device__ __forceinline__ uint32_t smem_u32(const void* p) {
    uint32_t a;
    asm("{ .reg .u64 t; cvta.to.shared.u64 t, %1; cvt.u32.u64 %0, t; }" : "=r"(a) : "l"(p));
    return a;
}
#define CP_ASYNC16(dst, src) \
    asm volatile("cp.async.cg.shared.global [%0], [%1], 16;" :: "r"(dst), "l"(src))
#define CP_COMMIT  asm volatile("cp.async.commit_group;")
#define CP_WAIT1   asm volatile("cp.async.wait_group 1;" ::: "memory")

// ================= tensor-core tf32 GEMM (cp.async double-buffered) =================
// C[128,128] tile = A[N,K] @ B[K,M]  (B in ORIGINAL row-major [K][M] layout)
// 128 threads = 4 warps, warp tile 64x64. K-chunks of 32, 2-stage pipeline.
// smem per stage: A 128x36 floats (pad: 36%32==4 -> conflict-free A frags)
//                 B  32x136 floats (pad: 136%32==8 -> conflict-free B frags)
#define TG_ASTRB 144            // A row stride bytes (36 floats)
#define TG_BSTRB 544            // B row stride bytes (136 floats)
#define TG_ABYTES (128 * 144)   // 18432
#define TG_STAGEB (TG_ABYTES + 32 * 544)  // 35840
#define TG_SMEM (2 * TG_STAGEB)           // 71680

#define TG_ISSUE(cc, ss) do {                                                        \
    uint32_t aoff = sbase + (uint32_t)(ss) * TG_STAGEB;                              \
    uint32_t boff = aoff + TG_ABYTES;                                                \
    int k0 = (cc) * 32;                                                              \
    _Pragma("unroll")                                                                \
    for (int j = 0; j < 8; j++) {                                                    \
        int idx = tid + 128 * j;                                                     \
        int ar = idx >> 3, aseg = idx & 7;                                           \
        CP_ASYNC16(aoff + (uint32_t)(ar * TG_ASTRB + aseg * 16),                     \
                   A + (size_t)(brow + ar) * K + k0 + aseg * 4);                     \
        int br = idx >> 5, bseg = idx & 31;                                          \
        CP_ASYNC16(boff + (uint32_t)(br * TG_BSTRB + bseg * 16),                     \
                   B + (size_t)(k0 + br) * Mtot + bcol + bseg * 4);                  \
    } } while (0)

template<int MODE>
__global__ void __launch_bounds__(128)
tgemm_kernel(const float* __restrict__ A, const float* __restrict__ B,
             const float* __restrict__ bias, const float* __restrict__ res,
             float* __restrict__ Cout, int K, int Mtot) {
    extern __shared__ float smem[];
    const uint32_t sbase = smem_u32(smem);

    const int tid  = threadIdx.x;
    const int wid  = tid >> 5;
    const int lane = tid & 31;
    const int lq   = lane >> 2, lr = lane & 3;
    const int wm   = wid & 1;       // 64-row half
    const int wn   = wid >> 1;      // 64-col half
    const int brow = blockIdx.x * 128;
    const int bcol = blockIdx.y * 128;

    float acc[128];
    #pragma unroll
    for (int i = 0; i < 128; i++) acc[i] = 0.f;

    const int nk = K >> 5;

    TG_ISSUE(0, 0);
    CP_COMMIT;

    for (int c = 0; c < nk; c++) {
        const int s = c & 1;
        if (c + 1 < nk) { TG_ISSUE(c + 1, (c + 1) & 1); }
        CP_COMMIT;
        CP_WAIT1;
        __syncthreads();

        const float* sA = smem + s * (TG_STAGEB / 4);
        const float* sB = sA + (TG_ABYTES / 4);

        #pragma unroll
        for (int q = 0; q < 4; q++) {
            uint32_t af[4][4];
            #pragma unroll
            for (int am = 0; am < 4; am++) {
                const float* ap = sA + (64 * wm + 16 * am + lq) * 36 + 8 * q + lr;
                af[am][0] = __float_as_uint(ap[0]);
                af[am][1] = __float_as_uint(ap[8 * 36]);
                af[am][2] = __float_as_uint(ap[4]);
                af[am][3] = __float_as_uint(ap[8 * 36 + 4]);
            }
            uint32_t bf[8][2];
            #pragma unroll
            for (int bn = 0; bn < 8; bn++) {
                const float* bp = sB + (8 * q + lr) * 136 + 64 * wn + 8 * bn + lq;
                bf[bn][0] = __float_as_uint(bp[0]);
                bf[bn][1] = __float_as_uint(bp[4 * 136]);
            }
            #pragma unroll
            for (int am = 0; am < 4; am++)
                #pragma unroll
                for (int bn = 0; bn < 8; bn++)
                    mma_tf32(&acc[(am * 8 + bn) * 4], af[am], bf[bn]);
        }
        __syncthreads();
    }

    // epilogue
    #pragma unroll
    for (int am = 0; am < 4; am++) {
        int row0 = brow + 64 * wm + 16 * am + lq;
        #pragma unroll
        for (int bn = 0; bn < 8; bn++) {
            int col = bcol + 64 * wn + 8 * bn + 2 * lr;
            float2 bv = *(const float2*)(bias + col);
            const int ix = (am * 8 + bn) * 4;
            float2 o0 = make_float2(acc[ix + 0] + bv.x, acc[ix + 1] + bv.y);
            float2 o1 = make_float2(acc[ix + 2] + bv.x, acc[ix + 3] + bv.y);
            if (MODE == 1) {
                float2 r0 = *(const float2*)(res + (size_t)row0 * Mtot + col);
                float2 r1 = *(const float2*)(res + (size_t)(row0 + 8) * Mtot + col);
                o0.x += r0.x; o0.y += r0.y; o1.x += r1.x; o1.y += r1.y;
            }
            if (MODE == 2) {
                o0.x = 0.5f * o0.x * (1.0f + erff(o0.x * 0.7071067811865476f));
                o0.y = 0.5f * o0.y * (1.0f + erff(o0.y * 0.7071067811865476f));
                o1.x = 0.5f * o1.x * (1.0f + erff(o1.x * 0.7071067811865476f));
                o1.y = 0.5f * o1.y * (1.0f + erff(o1.y * 0.7071067811865476f));
            }
            *(float2*)(Cout + (size_t)row0 * Mtot + col) = o0;
            *(float2*)(Cout + (size_t)(row0 + 8) * Mtot + col) = o1;
        }
    }
}

// ================= QKV weight/bias concat (no transpose needed anymore) =================
__global__ void __launch_bounds__(384) concat_qkv_kernel(const float* __restrict__ Wq,
                                                         const float* __restrict__ Wk,
                                                         const float* __restrict__ Wv) {
    int k = blockIdx.x;          // 0..383
    int t = threadIdx.x;         // 0..383
    g_wqkv[(size_t)k * QKVD + t]       = Wq[(size_t)k * CD + t];
    g_wqkv[(size_t)k * QKVD + 384 + t] = Wk[(size_t)k * CD + t];
    g_wqkv[(size_t)k * QKVD + 768 + t] = Wv[(size_t)k * CD + t];
}

__global__ void bias_concat_kernel(const float* bq, const float* bk, const float* bv) {
    int i = threadIdx.x + blockIdx.x * blockDim.x;
    if (i < 384) g_bqkv[i] = bq[i];
    else if (i < 768) g_bqkv[i] = bk[i - 384];
    else if (i < 1152) g_bqkv[i] = bv[i - 768];
}

// ================= gather (coalesced) + LN1 =================
__global__ void __launch_bounds__(384) gather_ln1_kernel(const float* __restrict__ x,
                                  const float* __restrict__ gamma,
                                  const float* __restrict__ beta) {
    __shared__ float s[384 * 9];
    __shared__ float smu[8], srs[8];

    int run = blockIdx.x;
    int p = run >> 5, td = (run >> 3) & 3, th = run & 7;
    int bd = p >> 6, bh = (p >> 3) & 7, bw = p & 7;
    int od = (bd * 4 + td + 2) & 15;
    int oh = (bh * 8 + th + 4) & 63;
    int w0 = (bw * 8 + 4) & 63;
    int w1 = (bw * 8 + 8) & 63;
    int n0 = p * 256 + td * 64 + th * 8;

    int c = threadIdx.x;
    const float* base = x + (size_t)c * DHW + od * HW + oh * 64;
    float4 fa = *(const float4*)(base + w0);
    float4 fb = *(const float4*)(base + w1);
    s[c * 9 + 0] = fa.x; s[c * 9 + 1] = fa.y; s[c * 9 + 2] = fa.z; s[c * 9 + 3] = fa.w;
    s[c * 9 + 4] = fb.x; s[c * 9 + 5] = fb.y; s[c * 9 + 6] = fb.z; s[c * 9 + 7] = fb.w;
    __syncthreads();

    int wid = c >> 5, lane = c & 31;
    if (wid < 8) {
        float sum = 0.f, sq = 0.f;
        #pragma unroll
        for (int i = 0; i < 12; i++) {
            float v = s[(lane + 32 * i) * 9 + wid];
            sum += v; sq += v * v;
        }
        #pragma unroll
        for (int o = 16; o; o >>= 1) {
            sum += __shfl_xor_sync(0xffffffffu, sum, o);
            sq  += __shfl_xor_sync(0xffffffffu, sq, o);
        }
        if (lane == 0) {
            float mu = sum * (1.f / 384.f);
            float var = sq * (1.f / 384.f) - mu * mu;
            smu[wid] = mu;
            srs[wid] = rsqrtf(var + 1e-5f);
        }
    }
    __syncthreads();

    float g = gamma[c], b = beta[c];
    #pragma unroll
    for (int j = 0; j < 8; j++) {
        float val = s[c * 9 + j];
        g_xw[(size_t)(n0 + j) * CD + c] = val;
        g_h [(size_t)(n0 + j) * CD + c] = (val - smu[j]) * srs[j] * g + b;
    }
}

// ================= LN2 =================
__global__ void ln2_kernel(const float* __restrict__ gamma,
                           const float* __restrict__ beta) {
    int n = blockIdx.x;
    int c = threadIdx.x;
    float val = g_xw2[n * CD + c];
    __shared__ float red[12];
    __shared__ float mu_s, rs_s;
    float s = val;
    #pragma unroll
    for (int o = 16; o; o >>= 1) s += __shfl_down_sync(0xffffffffu, s, o);
    if ((threadIdx.x & 31) == 0) red[threadIdx.x >> 5] = s;
    __syncthreads();
    if (threadIdx.x < 32) {
        float ts = (threadIdx.x < 12) ? red[threadIdx.x] : 0.f;
        #pragma unroll
        for (int o = 8; o; o >>= 1) ts += __shfl_down_sync(0xffffffffu, ts, o);
        if (threadIdx.x == 0) mu_s = ts * (1.f / 384.f);
    }
    __syncthreads();
    float d = val - mu_s;
    float s2 = d * d;
    #pragma unroll
    for (int o = 16; o; o >>= 1) s2 += __shfl_down_sync(0xffffffffu, s2, o);
    if ((threadIdx.x & 31) == 0) red[threadIdx.x >> 5] = s2;
    __syncthreads();
    if (threadIdx.x < 32) {
        float ts = (threadIdx.x < 12) ? red[threadIdx.x] : 0.f;
        #pragma unroll
        for (int o = 8; o; o >>= 1) ts += __shfl_down_sync(0xffffffffu, ts, o);
        if (threadIdx.x == 0) rs_s = rsqrtf(ts * (1.f / 384.f) + 1e-5f);
    }
    __syncthreads();
    g_h2[n * CD + c] = d * rs_s * gamma[c] + beta[c];
}

// ================= tensor-core flash attention =================
#define AQ_STR 68
#define AK_STR 68
#define AV_STR 72
#define AP_STR 68
#define SQ_OFF 0
#define SK_OFF (256 * AQ_STR)
#define SV_OFF (SK_OFF + 64 * AK_STR)
#define SP_OFF (SV_OFF + 64 * AV_STR)
#define ATT_SMEM ((SP_OFF + 256 * AP_STR) * 4)

__global__ void __launch_bounds__(256, 1) attn_tc_kernel() {
    extern __shared__ float sm[];
    float* sQ = sm + SQ_OFF;
    float* sK = sm + SK_OFF;
    float* sV = sm + SV_OFF;
    float* sP = sm + SP_OFF;

    const int p = blockIdx.x, h = blockIdx.y;
    const int tid = threadIdx.x;
    const int w = tid >> 5, lane = tid & 31;
    const int lq = lane >> 2, lr = lane & 3;

    {
        const float* qrow = g_qkv + (size_t)(p * 256 + tid) * QKVD + h * 64;
        #pragma unroll
        for (int k = 0; k < 16; k++) {
            float4 v = *(const float4*)(qrow + 4 * k);
            uint4 u = make_uint4(f2tf32(v.x), f2tf32(v.y), f2tf32(v.z), f2tf32(v.w));
            *(uint4*)&sQ[tid * AQ_STR + 4 * k] = u;
        }
    }

    float oacc[64];
    #pragma unroll
    for (int i = 0; i < 64; i++) oacc[i] = 0.f;
    float mrow[4] = {-1e30f, -1e30f, -1e30f, -1e30f};
    float lrow[4] = {0.f, 0.f, 0.f, 0.f};

    for (int kb = 0; kb < 4; kb++) {
        __syncthreads();
        {
            int r = tid >> 2, qt = tid & 3;
            const float* krow = g_qkv + (size_t)(p * 256 + kb * 64 + r) * QKVD + 384 + h * 64 + qt * 16;
            const float* vrow = krow + 384;
            #pragma unroll
            for (int e = 0; e < 4; e++) {
                float4 v = *(const float4*)(krow + 4 * e);
                *(uint4*)&sK[r * AK_STR + qt * 16 + 4 * e] =
                    make_uint4(f2tf32(v.x), f2tf32(v.y), f2tf32(v.z), f2tf32(v.w));
                float4 v2 = *(const float4*)(vrow + 4 * e);
                *(uint4*)&sV[r * AV_STR + qt * 16 + 4 * e] =
                    make_uint4(f2tf32(v2.x), f2tf32(v2.y), f2tf32(v2.z), f2tf32(v2.w));
            }
        }
        __syncthreads();

        float sacc[64];
        #pragma unroll
        for (int i = 0; i < 64; i++) sacc[i] = 0.f;
        #pragma unroll
        for (int q = 0; q < 8; q++) {
            uint32_t af[2][4];
            #pragma unroll
            for (int am = 0; am < 2; am++) {
                int R = 32 * w + 16 * am + lq;
                int col = lr + 8 * q;
                af[am][0] = __float_as_uint(sQ[R * AQ_STR + col]);
                af[am][1] = __float_as_uint(sQ[(R + 8) * AQ_STR + col]);
                af[am][2] = __float_as_uint(sQ[R * AQ_STR + col + 4]);
                af[am][3] = __float_as_uint(sQ[(R + 8) * AQ_STR + col + 4]);
            }
            uint32_t bf[8][2];
            #pragma unroll
            for (int bn = 0; bn < 8; bn++) {
                int key = 8 * bn + lq;
                bf[bn][0] = __float_as_uint(sK[key * AK_STR + lr + 8 * q]);
                bf[bn][1] = __float_as_uint(sK[key * AK_STR + lr + 4 + 8 * q]);
            }
            #pragma unroll
            for (int am = 0; am < 2; am++)
                #pragma unroll
                for (int bn = 0; bn < 8; bn++)
                    mma_tf32(&sacc[(am * 8 + bn) * 4], af[am], bf[bn]);
        }

        #pragma unroll
        for (int s = 0; s < 4; s++) {
            int am = s >> 1, hi = s & 1;
            float vmax = -1e30f;
            #pragma unroll
            for (int bn = 0; bn < 8; bn++) {
                float v0 = sacc[(am * 8 + bn) * 4 + 2 * hi] * 0.125f;
                float v1 = sacc[(am * 8 + bn) * 4 + 2 * hi + 1] * 0.125f;
                vmax = fmaxf(vmax, fmaxf(v0, v1));
            }
            vmax = fmaxf(vmax, __shfl_xor_sync(0xffffffffu, vmax, 1));
            vmax = fmaxf(vmax, __shfl_xor_sync(0xffffffffu, vmax, 2));
            float newm = fmaxf(mrow[s], vmax);
            float corr = __expf(mrow[s] - newm);
            mrow[s] = newm;
            float rsum = 0.f;
            int R = 32 * w + 16 * am + 8 * hi + lq;
            #pragma unroll
            for (int bn = 0; bn < 8; bn++) {
                float v0 = sacc[(am * 8 + bn) * 4 + 2 * hi] * 0.125f;
                float v1 = sacc[(am * 8 + bn) * 4 + 2 * hi + 1] * 0.125f;
                float p0 = __expf(v0 - newm), p1 = __expf(v1 - newm);
                rsum += p0 + p1;
                *(uint2*)&sP[R * AP_STR + 8 * bn + 2 * lr] = make_uint2(f2tf32(p0), f2tf32(p1));
            }
            rsum += __shfl_xor_sync(0xffffffffu, rsum, 1);
            rsum += __shfl_xor_sync(0xffffffffu, rsum, 2);
            lrow[s] = lrow[s] * corr + rsum;
            #pragma unroll
            for (int bn = 0; bn < 8; bn++) {
                oacc[(am * 8 + bn) * 4 + 2 * hi]     *= corr;
                oacc[(am * 8 + bn) * 4 + 2 * hi + 1] *= corr;
            }
        }
        __syncwarp();

        #pragma unroll
        for (int q = 0; q < 8; q++) {
            uint32_t af[2][4];
            #pragma unroll
            for (int am = 0; am < 2; am++) {
                int R = 32 * w + 16 * am + lq;
                int col = lr + 8 * q;
                af[am][0] = __float_as_uint(sP[R * AP_STR + col]);
                af[am][1] = __float_as_uint(sP[(R + 8) * AP_STR + col]);
                af[am][2] = __float_as_uint(sP[R * AP_STR + col + 4]);
                af[am][3] = __float_as_uint(sP[(R + 8) * AP_STR + col + 4]);
            }
            uint32_t bf[8][2];
            #pragma unroll
            for (int bn = 0; bn < 8; bn++) {
                int d = 8 * bn + lq;
                bf[bn][0] = __float_as_uint(sV[(8 * q + lr) * AV_STR + d]);
                bf[bn][1] = __float_as_uint(sV[(8 * q + lr + 4) * AV_STR + d]);
            }
            #pragma unroll
            for (int am = 0; am < 2; am++)
                #pragma unroll
                for (int bn = 0; bn < 8; bn++)
                    mma_tf32(&oacc[(am * 8 + bn) * 4], af[am], bf[bn]);
        }
    }

    float inv[4];
    #pragma unroll
    for (int s = 0; s < 4; s++) inv[s] = 1.f / lrow[s];
    #pragma unroll
    for (int am = 0; am < 2; am++) {
        int R0 = 32 * w + 16 * am + lq;
        #pragma unroll
        for (int bn = 0; bn < 8; bn++) {
            const int ix = (am * 8 + bn) * 4;
            *(float2*)&sP[R0 * AP_STR + 8 * bn + 2 * lr] =
                make_float2(oacc[ix + 0] * inv[2 * am], oacc[ix + 1] * inv[2 * am]);
            *(float2*)&sP[(R0 + 8) * AP_STR + 8 * bn + 2 * lr] =
                make_float2(oacc[ix + 2] * inv[2 * am + 1], oacc[ix + 3] * inv[2 * am + 1]);
        }
    }
    __syncthreads();
    {
        float* orow = g_att + (size_t)(p * 256 + tid) * CD + h * 64;
        #pragma unroll
        for (int k = 0; k < 16; k++)
            *(float4*)(orow + 4 * k) = *(const float4*)&sP[tid * AP_STR + 4 * k];
    }
}

// ================= scatter (coalesced) =================
__global__ void __launch_bounds__(384) scatter_kernel(float* __restrict__ out) {
    int run = blockIdx.x;
    int p = run >> 5, td = (run >> 3) & 3, th = run & 7;
    int bd = p >> 6, bh = (p >> 3) & 7, bw = p & 7;
    int od = (bd * 4 + td + 2) & 15;
    int oh = (bh * 8 + th + 4) & 63;
    int w0 = (bw * 8 + 4) & 63;
    int w1 = (bw * 8 + 8) & 63;
    int n0 = p * 256 + td * 64 + th * 8;

    int c = threadIdx.x;
    float v[8];
    #pragma unroll
    for (int j = 0; j < 8; j++) v[j] = g_y[(size_t)(n0 + j) * CD + c];
    float* base = out + (size_t)c * DHW + od * HW + oh * 64;
    *(float4*)(base + w0) = make_float4(v[0], v[1], v[2], v[3]);
    *(float4*)(base + w1) = make_float4(v[4], v[5], v[6], v[7]);
}

// ================= host launch =================
extern "C" void kernel_launch(void* const* d_in, const int* in_sizes, int n_in,
                              void* d_out, int out_size) {
    const float* x     = (const float*)d_in[0];
    const float* Wq    = (const float*)d_in[1];
    const float* bq    = (const float*)d_in[2];
    const float* Wk    = (const float*)d_in[3];
    const float* bk    = (const float*)d_in[4];
    const float* Wv    = (const float*)d_in[5];
    const float* bv    = (const float*)d_in[6];
    const float* Wo    = (const float*)d_in[7];
    const float* bo    = (const float*)d_in[8];
    const float* ln1_g = (const float*)d_in[9];
    const float* ln1_b = (const float*)d_in[10];
    const float* ln2_g = (const float*)d_in[11];
    const float* ln2_b = (const float*)d_in[12];
    const float* W1    = (const float*)d_in[13];
    const float* b1    = (const float*)d_in[14];
    const float* W2    = (const float*)d_in[15];
    const float* b2    = (const float*)d_in[16];
    float* out = (float*)d_out;

    float *p_h, *p_qkv, *p_att, *p_xw, *p_xw2, *p_h2, *p_hid, *p_y, *p_wqkv, *p_bqkv;
    cudaGetSymbolAddress((void**)&p_h,    g_h);
    cudaGetSymbolAddress((void**)&p_qkv,  g_qkv);
    cudaGetSymbolAddress((void**)&p_att,  g_att);
    cudaGetSymbolAddress((void**)&p_xw,   g_xw);
    cudaGetSymbolAddress((void**)&p_xw2,  g_xw2);
    cudaGetSymbolAddress((void**)&p_h2,   g_h2);
    cudaGetSymbolAddress((void**)&p_hid,  g_hid);
    cudaGetSymbolAddress((void**)&p_y,    g_y);
    cudaGetSymbolAddress((void**)&p_wqkv, g_wqkv);
    cudaGetSymbolAddress((void**)&p_bqkv, g_bqkv);

    cudaFuncSetAttribute(attn_tc_kernel, cudaFuncAttributeMaxDynamicSharedMemorySize, ATT_SMEM);
    cudaFuncSetAttribute(tgemm_kernel<0>, cudaFuncAttributeMaxDynamicSharedMemorySize, TG_SMEM);
    cudaFuncSetAttribute(tgemm_kernel<1>, cudaFuncAttributeMaxDynamicSharedMemorySize, TG_SMEM);
    cudaFuncSetAttribute(tgemm_kernel<2>, cudaFuncAttributeMaxDynamicSharedMemorySize, TG_SMEM);

    // 0) QKV weight/bias concat (no transposes needed)
    concat_qkv_kernel<<<384, 384>>>(Wq, Wk, Wv);
    bias_concat_kernel<<<3, 384>>>(bq, bk, bv);

    // 1) gather + LN1
    gather_ln1_kernel<<<8192, 384>>>(x, ln1_g, ln1_b);

    // 2) fused QKV projection
    tgemm_kernel<0><<<dim3(512, 9), 128, TG_SMEM>>>(p_h, p_wqkv, p_bqkv, nullptr, p_qkv, 384, QKVD);

    // 3) attention
    attn_tc_kernel<<<dim3(NWIN, NHEADS), 256, ATT_SMEM>>>();

    // 4) output projection + residual
    tgemm_kernel<1><<<dim3(512, 3), 128, TG_SMEM>>>(p_att, Wo, bo, p_xw, p_xw2, 384, 384);

    // 5) LN2
    ln2_kernel<<<NTOK, 384>>>(ln2_g, ln2_b);

    // 6) MLP
    tgemm_kernel<2><<<dim3(512, 12), 128, TG_SMEM>>>(p_h2, W1, b1, nullptr, p_hid, 384, MLPD);
    tgemm_kernel<1><<<dim3(512, 3), 128, TG_SMEM>>>(p_hid, W2, b2, p_xw2, p_y, MLPD, 384);

    // 7) scatter back
    scatter_kernel<<<8192, 384>>>(out);
}

// round 15
// speedup vs baseline: 4.1790x; 1.0230x over previous
#include <cuda_runtime.h>
#include <math.h>
#include <cstdint>

// Problem constants
#define CD   384
#define TWIN 256
#define NWIN 256
#define NTOK 65536
#define NHEADS 6
#define DHEAD 64
#define MLPD 1536
#define DHW 65536
#define HW 4096
#define QKVD 1152

// -------- scratch (device globals; allocation-free contract) --------
__device__ float g_xw [NTOK * CD];
__device__ float g_h  [NTOK * CD];
__device__ float g_qkv[(size_t)NTOK * QKVD];
__device__ float g_att[NTOK * CD];
__device__ float g_xw2[NTOK * CD];
__device__ float g_h2 [NTOK * CD];
__device__ float g_hid[(size_t)NTOK * MLPD];
__device__ float g_y  [NTOK * CD];
__device__ float g_wqkv[CD * QKVD];   // [K=384][M=1152] concat of Wq|Wk|Wv columns
__device__ float g_bqkv[QKVD];

// ---- helpers ----
__device__ __forceinline__ void mma_tf32(float* c, const uint32_t* a, const uint32_t* b) {
    asm volatile(
        "mma.sync.aligned.m16n8k8.row.col.f32.tf32.tf32.f32 "
        "{%0,%1,%2,%3}, {%4,%5,%6,%7}, {%8,%9}, {%0,%1,%2,%3};"
        : "+f"(c[0]), "+f"(c[1]), "+f"(c[2]), "+f"(c[3])
        : "r"(a[0]), "r"(a[1]), "r"(a[2]), "r"(a[3]), "r"(b[0]), "r"(b[1]));
}
__device__ __forceinline__ uint32_t smem_u32(const void* p) {
    uint32_t a;
    asm("{ .reg .u64 t; cvta.to.shared.u64 t, %1; cvt.u32.u64 %0, t; }" : "=r"(a) : "l"(p));
    return a;
}
#define CP_ASYNC16(dst, src) \
    asm volatile("cp.async.cg.shared.global [%0], [%1], 16;" :: "r"(dst), "l"(src))
#define CP_COMMIT  asm volatile("cp.async.commit_group;")
#define CP_WAIT1   asm volatile("cp.async.wait_group 1;" ::: "memory")

// ================= tensor-core tf32 GEMM (cp.async double-buffered) =================
// C[128,128] tile = A[N,K] @ B[K,M]  (B in ORIGINAL row-major [K][M] layout)
// 128 threads = 4 warps, warp tile 64x64. K-chunks of 32, 2-stage pipeline.
// Block mapping: bcol = blockIdx.x (FAST), brow = blockIdx.y (SLOW) so that
// consecutively-scheduled CTAs share the same A row-tile -> A stays in L2.
#define TG_ASTRB 144            // A row stride bytes (36 floats)
#define TG_BSTRB 544            // B row stride bytes (136 floats)
#define TG_ABYTES (128 * 144)   // 18432
#define TG_STAGEB (TG_ABYTES + 32 * 544)  // 35840
#define TG_SMEM (2 * TG_STAGEB)           // 71680

#define TG_ISSUE(cc, ss) do {                                                        \
    uint32_t aoff = sbase + (uint32_t)(ss) * TG_STAGEB;                              \
    uint32_t boff = aoff + TG_ABYTES;                                                \
    int k0 = (cc) * 32;                                                              \
    _Pragma("unroll")                                                                \
    for (int j = 0; j < 8; j++) {                                                    \
        int idx = tid + 128 * j;                                                     \
        int ar = idx >> 3, aseg = idx & 7;                                           \
        CP_ASYNC16(aoff + (uint32_t)(ar * TG_ASTRB + aseg * 16),                     \
                   A + (size_t)(brow + ar) * K + k0 + aseg * 4);                     \
        int br = idx >> 5, bseg = idx & 31;                                          \
        CP_ASYNC16(boff + (uint32_t)(br * TG_BSTRB + bseg * 16),                     \
                   B + (size_t)(k0 + br) * Mtot + bcol + bseg * 4);                  \
    } } while (0)

template<int MODE>
__global__ void __launch_bounds__(128)
tgemm_kernel(const float* __restrict__ A, const float* __restrict__ B,
             const float* __restrict__ bias, const float* __restrict__ res,
             float* __restrict__ Cout, int K, int Mtot) {
    extern __shared__ float smem[];
    const uint32_t sbase = smem_u32(smem);

    const int tid  = threadIdx.x;
    const int wid  = tid >> 5;
    const int lane = tid & 31;
    const int lq   = lane >> 2, lr = lane & 3;
    const int wm   = wid & 1;       // 64-row half
    const int wn   = wid >> 1;      // 64-col half
    const int brow = blockIdx.y * 128;   // SLOW index: A row tile shared by x-run
    const int bcol = blockIdx.x * 128;   // FAST index

    float acc[128];
    #pragma unroll
    for (int i = 0; i < 128; i++) acc[i] = 0.f;

    const int nk = K >> 5;

    TG_ISSUE(0, 0);
    CP_COMMIT;

    for (int c = 0; c < nk; c++) {
        const int s = c & 1;
        if (c + 1 < nk) { TG_ISSUE(c + 1, (c + 1) & 1); }
        CP_COMMIT;
        CP_WAIT1;
        __syncthreads();

        const float* sA = smem + s * (TG_STAGEB / 4);
        const float* sB = sA + (TG_ABYTES / 4);

        #pragma unroll
        for (int q = 0; q < 4; q++) {
            uint32_t af[4][4];
            #pragma unroll
            for (int am = 0; am < 4; am++) {
                const float* ap = sA + (64 * wm + 16 * am + lq) * 36 + 8 * q + lr;
                af[am][0] = __float_as_uint(ap[0]);
                af[am][1] = __float_as_uint(ap[8 * 36]);
                af[am][2] = __float_as_uint(ap[4]);
                af[am][3] = __float_as_uint(ap[8 * 36 + 4]);
            }
            uint32_t bf[8][2];
            #pragma unroll
            for (int bn = 0; bn < 8; bn++) {
                const float* bp = sB + (8 * q + lr) * 136 + 64 * wn + 8 * bn + lq;
                bf[bn][0] = __float_as_uint(bp[0]);
                bf[bn][1] = __float_as_uint(bp[4 * 136]);
            }
            #pragma unroll
            for (int am = 0; am < 4; am++)
                #pragma unroll
                for (int bn = 0; bn < 8; bn++)
                    mma_tf32(&acc[(am * 8 + bn) * 4], af[am], bf[bn]);
        }
        __syncthreads();
    }

    // epilogue
    #pragma unroll
    for (int am = 0; am < 4; am++) {
        int row0 = brow + 64 * wm + 16 * am + lq;
        #pragma unroll
        for (int bn = 0; bn < 8; bn++) {
            int col = bcol + 64 * wn + 8 * bn + 2 * lr;
            float2 bv = *(const float2*)(bias + col);
            const int ix = (am * 8 + bn) * 4;
            float2 o0 = make_float2(acc[ix + 0] + bv.x, acc[ix + 1] + bv.y);
            float2 o1 = make_float2(acc[ix + 2] + bv.x, acc[ix + 3] + bv.y);
            if (MODE == 1) {
                float2 r0 = *(const float2*)(res + (size_t)row0 * Mtot + col);
                float2 r1 = *(const float2*)(res + (size_t)(row0 + 8) * Mtot + col);
                o0.x += r0.x; o0.y += r0.y; o1.x += r1.x; o1.y += r1.y;
            }
            if (MODE == 2) {
                o0.x = 0.5f * o0.x * (1.0f + erff(o0.x * 0.7071067811865476f));
                o0.y = 0.5f * o0.y * (1.0f + erff(o0.y * 0.7071067811865476f));
                o1.x = 0.5f * o1.x * (1.0f + erff(o1.x * 0.7071067811865476f));
                o1.y = 0.5f * o1.y * (1.0f + erff(o1.y * 0.7071067811865476f));
            }
            *(float2*)(Cout + (size_t)row0 * Mtot + col) = o0;
            *(float2*)(Cout + (size_t)(row0 + 8) * Mtot + col) = o1;
        }
    }
}

// ================= QKV weight/bias concat =================
__global__ void __launch_bounds__(384) concat_qkv_kernel(const float* __restrict__ Wq,
                                                         const float* __restrict__ Wk,
                                                         const float* __restrict__ Wv) {
    int k = blockIdx.x;
    int t = threadIdx.x;
    g_wqkv[(size_t)k * QKVD + t]       = Wq[(size_t)k * CD + t];
    g_wqkv[(size_t)k * QKVD + 384 + t] = Wk[(size_t)k * CD + t];
    g_wqkv[(size_t)k * QKVD + 768 + t] = Wv[(size_t)k * CD + t];
}

__global__ void bias_concat_kernel(const float* bq, const float* bk, const float* bv) {
    int i = threadIdx.x + blockIdx.x * blockDim.x;
    if (i < 384) g_bqkv[i] = bq[i];
    else if (i < 768) g_bqkv[i] = bk[i - 384];
    else if (i < 1152) g_bqkv[i] = bv[i - 768];
}

// ================= gather (coalesced) + LN1 =================
__global__ void __launch_bounds__(384) gather_ln1_kernel(const float* __restrict__ x,
                                  const float* __restrict__ gamma,
                                  const float* __restrict__ beta) {
    __shared__ float s[384 * 9];
    __shared__ float smu[8], srs[8];

    int run = blockIdx.x;
    int p = run >> 5, td = (run >> 3) & 3, th = run & 7;
    int bd = p >> 6, bh = (p >> 3) & 7, bw = p & 7;
    int od = (bd * 4 + td + 2) & 15;
    int oh = (bh * 8 + th + 4) & 63;
    int w0 = (bw * 8 + 4) & 63;
    int w1 = (bw * 8 + 8) & 63;
    int n0 = p * 256 + td * 64 + th * 8;

    int c = threadIdx.x;
    const float* base = x + (size_t)c * DHW + od * HW + oh * 64;
    float4 fa = *(const float4*)(base + w0);
    float4 fb = *(const float4*)(base + w1);
    s[c * 9 + 0] = fa.x; s[c * 9 + 1] = fa.y; s[c * 9 + 2] = fa.z; s[c * 9 + 3] = fa.w;
    s[c * 9 + 4] = fb.x; s[c * 9 + 5] = fb.y; s[c * 9 + 6] = fb.z; s[c * 9 + 7] = fb.w;
    __syncthreads();

    int wid = c >> 5, lane = c & 31;
    if (wid < 8) {
        float sum = 0.f, sq = 0.f;
        #pragma unroll
        for (int i = 0; i < 12; i++) {
            float v = s[(lane + 32 * i) * 9 + wid];
            sum += v; sq += v * v;
        }
        #pragma unroll
        for (int o = 16; o; o >>= 1) {
            sum += __shfl_xor_sync(0xffffffffu, sum, o);
            sq  += __shfl_xor_sync(0xffffffffu, sq, o);
        }
        if (lane == 0) {
            float mu = sum * (1.f / 384.f);
            float var = sq * (1.f / 384.f) - mu * mu;
            smu[wid] = mu;
            srs[wid] = rsqrtf(var + 1e-5f);
        }
    }
    __syncthreads();

    float g = gamma[c], b = beta[c];
    #pragma unroll
    for (int j = 0; j < 8; j++) {
        float val = s[c * 9 + j];
        g_xw[(size_t)(n0 + j) * CD + c] = val;
        g_h [(size_t)(n0 + j) * CD + c] = (val - smu[j]) * srs[j] * g + b;
    }
}

// ================= LN2 =================
__global__ void ln2_kernel(const float* __restrict__ gamma,
                           const float* __restrict__ beta) {
    int n = blockIdx.x;
    int c = threadIdx.x;
    float val = g_xw2[n * CD + c];
    __shared__ float red[12];
    __shared__ float mu_s, rs_s;
    float s = val;
    #pragma unroll
    for (int o = 16; o; o >>= 1) s += __shfl_down_sync(0xffffffffu, s, o);
    if ((threadIdx.x & 31) == 0) red[threadIdx.x >> 5] = s;
    __syncthreads();
    if (threadIdx.x < 32) {
        float ts = (threadIdx.x < 12) ? red[threadIdx.x] : 0.f;
        #pragma unroll
        for (int o = 8; o; o >>= 1) ts += __shfl_down_sync(0xffffffffu, ts, o);
        if (threadIdx.x == 0) mu_s = ts * (1.f / 384.f);
    }
    __syncthreads();
    float d = val - mu_s;
    float s2 = d * d;
    #pragma unroll
    for (int o = 16; o; o >>= 1) s2 += __shfl_down_sync(0xffffffffu, s2, o);
    if ((threadIdx.x & 31) == 0) red[threadIdx.x >> 5] = s2;
    __syncthreads();
    if (threadIdx.x < 32) {
        float ts = (threadIdx.x < 12) ? red[threadIdx.x] : 0.f;
        #pragma unroll
        for (int o = 8; o; o >>= 1) ts += __shfl_down_sync(0xffffffffu, ts, o);
        if (threadIdx.x == 0) rs_s = rsqrtf(ts * (1.f / 384.f) + 1e-5f);
    }
    __syncthreads();
    g_h2[n * CD + c] = d * rs_s * gamma[c] + beta[c];
}

// ================= tensor-core flash attention (cp.async double-buffered) =================
#define AQ_STR 68
#define AK_STR 68
#define AV_STR 72
#define AP_STR 68
#define SK_OFF (256 * AQ_STR)                 // 17408 floats
#define A_STG  (64 * AK_STR + 64 * AV_STR)    // 8960 floats per KV stage
#define SP_OFF (SK_OFF + 2 * A_STG)           // 35328 floats
#define ATT_SMEM ((SP_OFF + 256 * AP_STR) * 4)  // 210944 bytes

// issue K/V block kb into stage ss (raw bits; cp.async)
#define ATT_ISSUE(kb, ss) do {                                                         \
    int r_ = tid >> 2, qt_ = tid & 3;                                                  \
    const float* krow_ = g_qkv + (size_t)(p * 256 + (kb) * 64 + r_) * QKVD + 384       \
                         + h * 64 + qt_ * 16;                                          \
    const float* vrow_ = krow_ + 384;                                                  \
    uint32_t ka_ = sb + (uint32_t)((SK_OFF + (ss) * A_STG + r_ * AK_STR + qt_ * 16) * 4); \
    uint32_t va_ = sb + (uint32_t)((SK_OFF + (ss) * A_STG + 64 * AK_STR + r_ * AV_STR + qt_ * 16) * 4); \
    _Pragma("unroll")                                                                  \
    for (int e_ = 0; e_ < 4; e_++) {                                                   \
        CP_ASYNC16(ka_ + 16 * e_, krow_ + 4 * e_);                                     \
        CP_ASYNC16(va_ + 16 * e_, vrow_ + 4 * e_);                                     \
    } } while (0)

__global__ void __launch_bounds__(256, 1) attn_tc_kernel() {
    extern __shared__ float sm[];
    const uint32_t sb = smem_u32(sm);
    float* sQ = sm;
    float* sP = sm + SP_OFF;

    const int p = blockIdx.x, h = blockIdx.y;
    const int tid = threadIdx.x;
    const int w = tid >> 5, lane = tid & 31;
    const int lq = lane >> 2, lr = lane & 3;

    // group 0: Q (raw) + KV block 0
    {
        const float* qrow = g_qkv + (size_t)(p * 256 + tid) * QKVD + h * 64;
        #pragma unroll
        for (int e = 0; e < 16; e++)
            CP_ASYNC16(sb + (uint32_t)((tid * AQ_STR + 4 * e) * 4), qrow + 4 * e);
        ATT_ISSUE(0, 0);
        CP_COMMIT;
    }

    float oacc[64];
    #pragma unroll
    for (int i = 0; i < 64; i++) oacc[i] = 0.f;
    float mrow[4] = {-1e30f, -1e30f, -1e30f, -1e30f};
    float lrow[4] = {0.f, 0.f, 0.f, 0.f};

    for (int kb = 0; kb < 4; kb++) {
        const int s = kb & 1;
        if (kb + 1 < 4) { ATT_ISSUE(kb + 1, (kb + 1) & 1); }
        CP_COMMIT;
        CP_WAIT1;
        __syncthreads();

        const float* sK = sm + SK_OFF + s * A_STG;
        const float* sV = sK + 64 * AK_STR;

        // S = Q_warp(32x64) @ K_blk^T(64x64)
        float sacc[64];
        #pragma unroll
        for (int i = 0; i < 64; i++) sacc[i] = 0.f;
        #pragma unroll
        for (int q = 0; q < 8; q++) {
            uint32_t af[2][4];
            #pragma unroll
            for (int am = 0; am < 2; am++) {
                int R = 32 * w + 16 * am + lq;
                int col = lr + 8 * q;
                af[am][0] = __float_as_uint(sQ[R * AQ_STR + col]);
                af[am][1] = __float_as_uint(sQ[(R + 8) * AQ_STR + col]);
                af[am][2] = __float_as_uint(sQ[R * AQ_STR + col + 4]);
                af[am][3] = __float_as_uint(sQ[(R + 8) * AQ_STR + col + 4]);
            }
            uint32_t bf[8][2];
            #pragma unroll
            for (int bn = 0; bn < 8; bn++) {
                int key = 8 * bn + lq;
                bf[bn][0] = __float_as_uint(sK[key * AK_STR + lr + 8 * q]);
                bf[bn][1] = __float_as_uint(sK[key * AK_STR + lr + 4 + 8 * q]);
            }
            #pragma unroll
            for (int am = 0; am < 2; am++)
                #pragma unroll
                for (int bn = 0; bn < 8; bn++)
                    mma_tf32(&sacc[(am * 8 + bn) * 4], af[am], bf[bn]);
        }

        // online softmax per row-slot (P stored raw)
        #pragma unroll
        for (int s4 = 0; s4 < 4; s4++) {
            int am = s4 >> 1, hi = s4 & 1;
            float vmax = -1e30f;
            #pragma unroll
            for (int bn = 0; bn < 8; bn++) {
                float v0 = sacc[(am * 8 + bn) * 4 + 2 * hi] * 0.125f;
                float v1 = sacc[(am * 8 + bn) * 4 + 2 * hi + 1] * 0.125f;
                vmax = fmaxf(vmax, fmaxf(v0, v1));
            }
            vmax = fmaxf(vmax, __shfl_xor_sync(0xffffffffu, vmax, 1));
            vmax = fmaxf(vmax, __shfl_xor_sync(0xffffffffu, vmax, 2));
            float newm = fmaxf(mrow[s4], vmax);
            float corr = __expf(mrow[s4] - newm);
            mrow[s4] = newm;
            float rsum = 0.f;
            int R = 32 * w + 16 * am + 8 * hi + lq;
            #pragma unroll
            for (int bn = 0; bn < 8; bn++) {
                float v0 = sacc[(am * 8 + bn) * 4 + 2 * hi] * 0.125f;
                float v1 = sacc[(am * 8 + bn) * 4 + 2 * hi + 1] * 0.125f;
                float p0 = __expf(v0 - newm), p1 = __expf(v1 - newm);
                rsum += p0 + p1;
                *(float2*)&sP[R * AP_STR + 8 * bn + 2 * lr] = make_float2(p0, p1);
            }
            rsum += __shfl_xor_sync(0xffffffffu, rsum, 1);
            rsum += __shfl_xor_sync(0xffffffffu, rsum, 2);
            lrow[s4] = lrow[s4] * corr + rsum;
            #pragma unroll
            for (int bn = 0; bn < 8; bn++) {
                oacc[(am * 8 + bn) * 4 + 2 * hi]     *= corr;
                oacc[(am * 8 + bn) * 4 + 2 * hi + 1] *= corr;
            }
        }
        __syncwarp();

        // O += P(32x64) @ V(64x64)
        #pragma unroll
        for (int q = 0; q < 8; q++) {
            uint32_t af[2][4];
            #pragma unroll
            for (int am = 0; am < 2; am++) {
                int R = 32 * w + 16 * am + lq;
                int col = lr + 8 * q;
                af[am][0] = __float_as_uint(sP[R * AP_STR + col]);
                af[am][1] = __float_as_uint(sP[(R + 8) * AP_STR + col]);
                af[am][2] = __float_as_uint(sP[R * AP_STR + col + 4]);
                af[am][3] = __float_as_uint(sP[(R + 8) * AP_STR + col + 4]);
            }
            uint32_t bf[8][2];
            #pragma unroll
            for (int bn = 0; bn < 8; bn++) {
                int d = 8 * bn + lq;
                bf[bn][0] = __float_as_uint(sV[(8 * q + lr) * AV_STR + d]);
                bf[bn][1] = __float_as_uint(sV[(8 * q + lr + 4) * AV_STR + d]);
            }
            #pragma unroll
            for (int am = 0; am < 2; am++)
                #pragma unroll
                for (int bn = 0; bn < 8; bn++)
                    mma_tf32(&oacc[(am * 8 + bn) * 4], af[am], bf[bn]);
        }
        __syncthreads();   // all reads of stage s done before it is overwritten
    }

    float inv[4];
    #pragma unroll
    for (int s4 = 0; s4 < 4; s4++) inv[s4] = 1.f / lrow[s4];
    #pragma unroll
    for (int am = 0; am < 2; am++) {
        int R0 = 32 * w + 16 * am + lq;
        #pragma unroll
        for (int bn = 0; bn < 8; bn++) {
            const int ix = (am * 8 + bn) * 4;
            *(float2*)&sP[R0 * AP_STR + 8 * bn + 2 * lr] =
                make_float2(oacc[ix + 0] * inv[2 * am], oacc[ix + 1] * inv[2 * am]);
            *(float2*)&sP[(R0 + 8) * AP_STR + 8 * bn + 2 * lr] =
                make_float2(oacc[ix + 2] * inv[2 * am + 1], oacc[ix + 3] * inv[2 * am + 1]);
        }
    }
    __syncthreads();
    {
        float* orow = g_att + (size_t)(p * 256 + tid) * CD + h * 64;
        #pragma unroll
        for (int k = 0; k < 16; k++)
            *(float4*)(orow + 4 * k) = *(const float4*)&sP[tid * AP_STR + 4 * k];
    }
}

// ================= scatter (coalesced) =================
__global__ void __launch_bounds__(384) scatter_kernel(float* __restrict__ out) {
    int run = blockIdx.x;
    int p = run >> 5, td = (run >> 3) & 3, th = run & 7;
    int bd = p >> 6, bh = (p >> 3) & 7, bw = p & 7;
    int od = (bd * 4 + td + 2) & 15;
    int oh = (bh * 8 + th + 4) & 63;
    int w0 = (bw * 8 + 4) & 63;
    int w1 = (bw * 8 + 8) & 63;
    int n0 = p * 256 + td * 64 + th * 8;

    int c = threadIdx.x;
    float v[8];
    #pragma unroll
    for (int j = 0; j < 8; j++) v[j] = g_y[(size_t)(n0 + j) * CD + c];
    float* base = out + (size_t)c * DHW + od * HW + oh * 64;
    *(float4*)(base + w0) = make_float4(v[0], v[1], v[2], v[3]);
    *(float4*)(base + w1) = make_float4(v[4], v[5], v[6], v[7]);
}

// ================= host launch =================
extern "C" void kernel_launch(void* const* d_in, const int* in_sizes, int n_in,
                              void* d_out, int out_size) {
    const float* x     = (const float*)d_in[0];
    const float* Wq    = (const float*)d_in[1];
    const float* bq    = (const float*)d_in[2];
    const float* Wk    = (const float*)d_in[3];
    const float* bk    = (const float*)d_in[4];
    const float* Wv    = (const float*)d_in[5];
    const float* bv    = (const float*)d_in[6];
    const float* Wo    = (const float*)d_in[7];
    const float* bo    = (const float*)d_in[8];
    const float* ln1_g = (const float*)d_in[9];
    const float* ln1_b = (const float*)d_in[10];
    const float* ln2_g = (const float*)d_in[11];
    const float* ln2_b = (const float*)d_in[12];
    const float* W1    = (const float*)d_in[13];
    const float* b1    = (const float*)d_in[14];
    const float* W2    = (const float*)d_in[15];
    const float* b2    = (const float*)d_in[16];
    float* out = (float*)d_out;

    float *p_h, *p_qkv, *p_att, *p_xw, *p_xw2, *p_h2, *p_hid, *p_y, *p_wqkv, *p_bqkv;
    cudaGetSymbolAddress((void**)&p_h,    g_h);
    cudaGetSymbolAddress((void**)&p_qkv,  g_qkv);
    cudaGetSymbolAddress((void**)&p_att,  g_att);
    cudaGetSymbolAddress((void**)&p_xw,   g_xw);
    cudaGetSymbolAddress((void**)&p_xw2,  g_xw2);
    cudaGetSymbolAddress((void**)&p_h2,   g_h2);
    cudaGetSymbolAddress((void**)&p_hid,  g_hid);
    cudaGetSymbolAddress((void**)&p_y,    g_y);
    cudaGetSymbolAddress((void**)&p_wqkv, g_wqkv);
    cudaGetSymbolAddress((void**)&p_bqkv, g_bqkv);

    cudaFuncSetAttribute(attn_tc_kernel, cudaFuncAttributeMaxDynamicSharedMemorySize, ATT_SMEM);
    cudaFuncSetAttribute(tgemm_kernel<0>, cudaFuncAttributeMaxDynamicSharedMemorySize, TG_SMEM);
    cudaFuncSetAttribute(tgemm_kernel<1>, cudaFuncAttributeMaxDynamicSharedMemorySize, TG_SMEM);
    cudaFuncSetAttribute(tgemm_kernel<2>, cudaFuncAttributeMaxDynamicSharedMemorySize, TG_SMEM);

    // 0) QKV weight/bias concat
    concat_qkv_kernel<<<384, 384>>>(Wq, Wk, Wv);
    bias_concat_kernel<<<3, 384>>>(bq, bk, bv);

    // 1) gather + LN1
    gather_ln1_kernel<<<8192, 384>>>(x, ln1_g, ln1_b);

    // 2) fused QKV projection  (grid: x = col tiles FAST, y = row tiles)
    tgemm_kernel<0><<<dim3(9, 512), 128, TG_SMEM>>>(p_h, p_wqkv, p_bqkv, nullptr, p_qkv, 384, QKVD);

    // 3) attention
    attn_tc_kernel<<<dim3(NWIN, NHEADS), 256, ATT_SMEM>>>();

    // 4) output projection + residual
    tgemm_kernel<1><<<dim3(3, 512), 128, TG_SMEM>>>(p_att, Wo, bo, p_xw, p_xw2, 384, 384);

    // 5) LN2
    ln2_kernel<<<NTOK, 384>>>(ln2_g, ln2_b);

    // 6) MLP
    tgemm_kernel<2><<<dim3(12, 512), 128, TG_SMEM>>>(p_h2, W1, b1, nullptr, p_hid, 384, MLPD);
    tgemm_kernel<1><<<dim3(3, 512), 128, TG_SMEM>>>(p_hid, W2, b2, p_xw2, p_y, MLPD, 384);

    // 7) scatter back
    scatter_kernel<<<8192, 384>>>(out);
}